// round 14
// baseline (speedup 1.0000x reference)
#include <cuda_runtime.h>
#include <cuda_bf16.h>
#include <cstdint>

// ---------------- problem constants ----------------
#define B_   2
#define S_   2048
#define HID_ 2048
#define H_   16
#define QL_  1536
#define KVL_ 512
#define DN_  128
#define DR_  64
#define DV_  128
#define DQK_ 192
#define NT_  (B_*S_)        // 4096 tokens

typedef __nv_bfloat16 bf16;

// ---------------- scratch (static device globals; no alloc) ----------------
__device__ __align__(128) float g_qan[(size_t)NT_ * QL_];
__device__ __align__(128) float g_kvall[(size_t)NT_ * (KVL_ + DR_)];

__device__ __align__(128) bf16 g_xhi[(size_t)NT_ * HID_],  g_xlo[(size_t)NT_ * HID_];
__device__ __align__(128) bf16 g_qanhi[(size_t)NT_ * QL_], g_qanlo[(size_t)NT_ * QL_];
__device__ __align__(128) bf16 g_kvnhi[(size_t)NT_ * KVL_],g_kvnlo[(size_t)NT_ * KVL_];
__device__ __align__(128) bf16 g_athi[(size_t)NT_ * (H_*DV_)], g_atlo[(size_t)NT_ * (H_*DV_)];
__device__ __align__(128) bf16 g_wqahi[(size_t)QL_ * HID_],        g_wqalo[(size_t)QL_ * HID_];
__device__ __align__(128) bf16 g_wqbhi[(size_t)(H_*DQK_) * QL_],   g_wqblo[(size_t)(H_*DQK_) * QL_];
__device__ __align__(128) bf16 g_wkvahi[(size_t)(KVL_+DR_) * HID_],g_wkvalo[(size_t)(KVL_+DR_) * HID_];
__device__ __align__(128) bf16 g_wkvbhi[(size_t)(H_*256) * KVL_],  g_wkvblo[(size_t)(H_*256) * KVL_];
__device__ __align__(128) bf16 g_wohi[(size_t)HID_ * (H_*DV_)],    g_wolo[(size_t)HID_ * (H_*DV_)];

// attention operand planes, packed per head
__device__ __align__(128) bf16 g_aqhi[(size_t)NT_ * H_ * DQK_], g_aqlo[(size_t)NT_ * H_ * DQK_];
__device__ __align__(128) bf16 g_akhi[(size_t)NT_ * H_ * DQK_], g_aklo[(size_t)NT_ * H_ * DQK_];
__device__ __align__(128) bf16 g_avhi[(size_t)NT_ * H_ * DV_],  g_avlo[(size_t)NT_ * H_ * DV_];

// ================= PTX helpers (baseline compute_103 features only) =========
__device__ __forceinline__ uint32_t smem_u32(const void* p) {
    uint32_t a;
    asm("{ .reg .u64 t; cvta.to.shared.u64 t, %1; cvt.u32.u64 %0, t; }" : "=r"(a) : "l"(p));
    return a;
}
__device__ __forceinline__ void cp_async16(uint32_t dst, const void* src, int src_bytes) {
    asm volatile("cp.async.cg.shared.global [%0], [%1], 16, %2;"
                 :: "r"(dst), "l"(src), "r"(src_bytes) : "memory");
}
__device__ __forceinline__ void cp_commit() {
    asm volatile("cp.async.commit_group;" ::: "memory");
}
template <int N>
__device__ __forceinline__ void cp_wait() {
    asm volatile("cp.async.wait_group %0;" :: "n"(N) : "memory");
}
__device__ __forceinline__ void ldmx4(uint32_t* r, uint32_t addr) {
    asm volatile("ldmatrix.sync.aligned.m8n8.x4.shared.b16 {%0,%1,%2,%3}, [%4];"
                 : "=r"(r[0]), "=r"(r[1]), "=r"(r[2]), "=r"(r[3]) : "r"(addr));
}
__device__ __forceinline__ void ldmx4t(uint32_t* r, uint32_t addr) {
    asm volatile("ldmatrix.sync.aligned.m8n8.x4.trans.shared.b16 {%0,%1,%2,%3}, [%4];"
                 : "=r"(r[0]), "=r"(r[1]), "=r"(r[2]), "=r"(r[3]) : "r"(addr));
}
__device__ __forceinline__ void mma16816(float* c, const uint32_t* a, uint32_t b0, uint32_t b1) {
    asm("mma.sync.aligned.m16n8k16.row.col.f32.bf16.bf16.f32 "
        "{%0,%1,%2,%3}, {%4,%5,%6,%7}, {%8,%9}, {%0,%1,%2,%3};"
        : "+f"(c[0]), "+f"(c[1]), "+f"(c[2]), "+f"(c[3])
        : "r"(a[0]), "r"(a[1]), "r"(a[2]), "r"(a[3]), "r"(b0), "r"(b1));
}
__device__ __forceinline__ uint32_t packbf(float x, float y) {
    uint32_t r;
    asm("cvt.rn.bf16x2.f32 %0, %1, %2;" : "=r"(r) : "f"(y), "f"(x));
    return r;
}
__device__ __forceinline__ void split2(float x, float y, uint32_t& hi, uint32_t& lo) {
    float xh = __bfloat162float(__float2bfloat16(x));
    float yh = __bfloat162float(__float2bfloat16(y));
    hi = packbf(xh, yh);
    lo = packbf(x - xh, y - yh);
}

// ================= HMMA split-bf16 GEMM ======================================
// CTA tile 128x128, 4 warps (128 thr) of 64x64, 2 CTAs/SM, 2-stage pipeline.
// B fragments loaded as single ldmx4 spanning both kf halves (32 LDSM/chunk).
#define GBK 32
#define ROWB 80
#define APL 10240                  // plane: 128 rows * 80B
#define GBUF (4 * APL)             // Ah,Al,Bh,Bl = 40960 B per stage
#define GSMEM (2 * GBUF)           // 81920 B

struct Seg {
    const bf16 *Ah, *Al, *Wh, *Wl;
    float* C;
    bf16 *P1, *P2, *P3, *P4;
    const float* fc;
    int N, K, ldc, gx, epi;   // epi: 0=fp32 C, 1=Q(scale+rope+split), 2=KV split
};

__device__ __forceinline__ void load_tile(
    const bf16* __restrict__ g, int ld, int rowbase, int rowlim,
    int kcol, uint32_t sdst, int tid)
{
#pragma unroll
    for (int i = 0; i < 4; ++i) {
        int idx = tid + i * 128;
        int r = idx >> 2;
        int c8 = (idx & 3) << 3;
        int gr = rowbase + r;
        int ok = (gr < rowlim);
        const bf16* src = g + (size_t)(ok ? gr : rowbase) * ld + kcol + c8;
        cp_async16(sdst + r * ROWB + c8 * 2, src, ok ? 16 : 0);
    }
}

extern __shared__ uint8_t dsm[];

__global__ __launch_bounds__(128, 2) void gemm_hmma(Seg s0, Seg s1, int nb0)
{
    const Seg s = (blockIdx.x < (unsigned)nb0) ? s0 : s1;
    const int bid = (blockIdx.x < (unsigned)nb0) ? blockIdx.x : blockIdx.x - nb0;
    const int tid  = threadIdx.x;
    const int wid  = tid >> 5;
    const int lane = tid & 31;
    const int bm = (bid / s.gx) * 128;
    const int bn = (bid % s.gx) * 128;
    const int wm = (wid & 1) * 64;        // 2 warps in M
    const int wn = (wid >> 1) * 64;       // 2 warps in N
    const uint32_t sb = smem_u32(dsm);

    float acc[4][8][4];
#pragma unroll
    for (int i = 0; i < 4; i++)
#pragma unroll
        for (int j = 0; j < 8; j++)
#pragma unroll
            for (int k = 0; k < 4; k++) acc[i][j][k] = 0.f;

    const int nchunks = s.K / GBK;

    {
        uint32_t buf = sb;
        load_tile(s.Ah, s.K, bm, 1 << 30, 0, buf,           tid);
        load_tile(s.Al, s.K, bm, 1 << 30, 0, buf + APL,     tid);
        load_tile(s.Wh, s.K, bn, s.N,     0, buf + 2 * APL, tid);
        load_tile(s.Wl, s.K, bn, s.N,     0, buf + 3 * APL, tid);
        cp_commit();
    }

    const uint32_t a_off = (uint32_t)((wm + (lane & 15)) * ROWB + ((lane >> 4) << 3) * 2);
    // B x4: lane groups 0..3 cover k-bytes 0,16,32,48 (both kf halves)
    const uint32_t b_off = (uint32_t)((wn + (lane & 7)) * ROWB + (lane >> 3) * 16);

    for (int c = 0; c < nchunks; ++c) {
        cp_wait<0>();
        __syncthreads();              // single barrier per chunk

        if (c + 1 < nchunks) {
            uint32_t buf = sb + ((c + 1) & 1) * GBUF;
            int kcol = (c + 1) * GBK;
            load_tile(s.Ah, s.K, bm, 1 << 30, kcol, buf,           tid);
            load_tile(s.Al, s.K, bm, 1 << 30, kcol, buf + APL,     tid);
            load_tile(s.Wh, s.K, bn, s.N,     kcol, buf + 2 * APL, tid);
            load_tile(s.Wl, s.K, bn, s.N,     kcol, buf + 3 * APL, tid);
            cp_commit();
        }

        const uint32_t buf = sb + (c & 1) * GBUF;

        // A fragments for both kf halves, cached for the whole chunk
        uint32_t afr[2][4][2][4];     // [plane][mi][kf][4]
#pragma unroll
        for (int pl = 0; pl < 2; ++pl)
#pragma unroll
            for (int mi = 0; mi < 4; ++mi)
#pragma unroll
                for (int kf = 0; kf < 2; ++kf)
                    ldmx4(afr[pl][mi][kf],
                          buf + pl * APL + a_off + mi * 16 * ROWB + kf * 32);

#pragma unroll
        for (int ni = 0; ni < 8; ++ni) {
            uint32_t bh[4], bl[4];    // [kf0 b0,b1, kf1 b0,b1]
            ldmx4(bh, buf + 2 * APL + b_off + ni * 8 * ROWB);
            ldmx4(bl, buf + 3 * APL + b_off + ni * 8 * ROWB);
            // per-acc order: kf0 (hh,hl,lh) then kf1 (hh,hl,lh) - identical to R13
#pragma unroll
            for (int kf = 0; kf < 2; ++kf) {
#pragma unroll
                for (int mi = 0; mi < 4; ++mi) {
                    float* d = acc[mi][ni];
                    mma16816(d, afr[0][mi][kf], bh[kf*2], bh[kf*2+1]);   // hi*hi
                    mma16816(d, afr[0][mi][kf], bl[kf*2], bl[kf*2+1]);   // hi*lo
                    mma16816(d, afr[1][mi][kf], bh[kf*2], bh[kf*2+1]);   // lo*hi
                }
            }
        }
    }

    // -------- epilogues --------
    const int r0 = bm + wm + (lane >> 2);
    const int cb = bn + wn + (lane & 3) * 2;

    if (s.epi == 0) {
#pragma unroll
        for (int mi = 0; mi < 4; ++mi)
#pragma unroll
            for (int ni = 0; ni < 8; ++ni) {
                int col = cb + ni * 8;
                if (col < s.N) {
                    int row = r0 + mi * 16;
                    *reinterpret_cast<float2*>(&s.C[(size_t)row * s.ldc + col]) =
                        make_float2(acc[mi][ni][0], acc[mi][ni][1]);
                    *reinterpret_cast<float2*>(&s.C[(size_t)(row + 8) * s.ldc + col]) =
                        make_float2(acc[mi][ni][2], acc[mi][ni][3]);
                }
            }
    } else if (s.epi == 1) {
        const float sc = 0.07216878364870323f;   // 1/sqrt(192)
#pragma unroll
        for (int mi = 0; mi < 4; ++mi)
#pragma unroll
            for (int ni = 0; ni < 8; ++ni) {
                int col = cb + ni * 8;
                int row = r0 + mi * 16;
                int d = col % 192;
                float a0 = acc[mi][ni][0], a1 = acc[mi][ni][1];
                float a2 = acc[mi][ni][2], a3 = acc[mi][ni][3];
                if (d >= 128) {
                    int p = (d - 128) >> 1;
                    int sA = row & (S_ - 1), sB = (row + 8) & (S_ - 1);
                    float cA = s.fc[(sA * 32 + p) * 2], snA = s.fc[(sA * 32 + p) * 2 + 1];
                    float cB = s.fc[(sB * 32 + p) * 2], snB = s.fc[(sB * 32 + p) * 2 + 1];
                    float t0 = a0 * cA - a1 * snA, t1 = a0 * snA + a1 * cA;
                    float t2 = a2 * cB - a3 * snB, t3 = a2 * snB + a3 * cB;
                    a0 = t0; a1 = t1; a2 = t2; a3 = t3;
                }
                a0 *= sc; a1 *= sc; a2 *= sc; a3 *= sc;
                uint32_t hh, ll;
                split2(a0, a1, hh, ll);
                *reinterpret_cast<uint32_t*>(&s.P1[(size_t)row * 3072 + col]) = hh;
                *reinterpret_cast<uint32_t*>(&s.P2[(size_t)row * 3072 + col]) = ll;
                split2(a2, a3, hh, ll);
                *reinterpret_cast<uint32_t*>(&s.P1[(size_t)(row + 8) * 3072 + col]) = hh;
                *reinterpret_cast<uint32_t*>(&s.P2[(size_t)(row + 8) * 3072 + col]) = ll;
            }
    } else {
#pragma unroll
        for (int mi = 0; mi < 4; ++mi)
#pragma unroll
            for (int ni = 0; ni < 8; ++ni) {
                int col = cb + ni * 8;
                int row = r0 + mi * 16;
                int h = col >> 8, d = col & 255;
                bf16 *H, *L;
                size_t idx; size_t st;
                if (d < 128) { idx = ((size_t)row * 16 + h) * 192 + d;        st = (size_t)8 * 16 * 192; H = s.P1; L = s.P2; }
                else         { idx = ((size_t)row * 16 + h) * 128 + (d - 128); st = (size_t)8 * 16 * 128; H = s.P3; L = s.P4; }
                uint32_t hh, ll;
                split2(acc[mi][ni][0], acc[mi][ni][1], hh, ll);
                *reinterpret_cast<uint32_t*>(&H[idx]) = hh;
                *reinterpret_cast<uint32_t*>(&L[idx]) = ll;
                split2(acc[mi][ni][2], acc[mi][ni][3], hh, ll);
                *reinterpret_cast<uint32_t*>(&H[idx + st]) = hh;
                *reinterpret_cast<uint32_t*>(&L[idx + st]) = ll;
            }
    }
}

// ================= converts (single merged launch) =================
struct CTab {
    const float* s[6];
    bf16 *h[6], *l[6];
    unsigned n4[6];
    unsigned start[7];
};

__global__ void convert_all(CTab t)
{
    unsigned b = blockIdx.x;
    int k = 0;
#pragma unroll
    for (int j = 1; j < 6; j++) if (b >= t.start[j]) k = j;
    size_t i = (size_t)(b - t.start[k]) * 256 + threadIdx.x;
    if (i >= t.n4[k]) return;
    float4 v = reinterpret_cast<const float4*>(t.s[k])[i];
    bf16 h0 = __float2bfloat16(v.x), h1 = __float2bfloat16(v.y);
    bf16 h2 = __float2bfloat16(v.z), h3 = __float2bfloat16(v.w);
    bf16 l0 = __float2bfloat16(v.x - __bfloat162float(h0));
    bf16 l1 = __float2bfloat16(v.y - __bfloat162float(h1));
    bf16 l2 = __float2bfloat16(v.z - __bfloat162float(h2));
    bf16 l3 = __float2bfloat16(v.w - __bfloat162float(h3));
    __nv_bfloat162* hp = reinterpret_cast<__nv_bfloat162*>(t.h[k]);
    __nv_bfloat162* lp = reinterpret_cast<__nv_bfloat162*>(t.l[k]);
    hp[2*i]   = __nv_bfloat162(h0, h1); hp[2*i+1] = __nv_bfloat162(h2, h3);
    lp[2*i]   = __nv_bfloat162(l0, l1); lp[2*i+1] = __nv_bfloat162(l2, l3);
}

// ---------- merged RMSNorm(q) + RMSNorm(kv) + k_pe rope/broadcast ----------
__global__ void rmsnorm_both(
    const float* __restrict__ qan, const float* __restrict__ qw,
    bf16* __restrict__ qhi, bf16* __restrict__ qlo,
    const float* __restrict__ kvall, const float* __restrict__ kvw,
    bf16* __restrict__ kvhi, bf16* __restrict__ kvlo,
    const float* __restrict__ fc,
    bf16* __restrict__ akhi, bf16* __restrict__ aklo)
{
    __shared__ float red[256];
    const int blk = blockIdx.x;
    const int isq = (blk < NT_);
    const int row = isq ? blk : blk - NT_;
    const int n = isq ? QL_ : KVL_;
    const float* p = isq ? qan + (size_t)row * QL_
                         : kvall + (size_t)row * (KVL_ + DR_);
    const float* w = isq ? qw : kvw;
    bf16* hi = isq ? qhi : kvhi;
    bf16* lo = isq ? qlo : kvlo;

    float sacc = 0.f;
    for (int i = threadIdx.x; i < n; i += 256) { float v = p[i]; sacc += v * v; }
    red[threadIdx.x] = sacc;
    __syncthreads();
    for (int o = 128; o > 0; o >>= 1) {
        if (threadIdx.x < o) red[threadIdx.x] += red[threadIdx.x + o];
        __syncthreads();
    }
    float inv = rsqrtf(red[0] / n + 1e-6f);
    for (int i = threadIdx.x * 2; i < n; i += 512) {
        float v0 = p[i] * inv * w[i];
        float v1 = p[i + 1] * inv * w[i + 1];
        uint32_t hh, ll;
        split2(v0, v1, hh, ll);
        *reinterpret_cast<uint32_t*>(&hi[(size_t)row * n + i]) = hh;
        *reinterpret_cast<uint32_t*>(&lo[(size_t)row * n + i]) = ll;
    }

    if (!isq && threadIdx.x < 32) {
        const int pr = threadIdx.x;
        const int sfx = row & (S_ - 1);
        float xr = p[KVL_ + 2 * pr];
        float xi = p[KVL_ + 2 * pr + 1];
        float c = fc[(sfx * 32 + pr) * 2], sn = fc[(sfx * 32 + pr) * 2 + 1];
        float r0 = xr * c - xi * sn, r1 = xr * sn + xi * c;
        uint32_t hh, ll;
        split2(r0, r1, hh, ll);
        size_t base = ((size_t)row * 16) * 192 + 128 + 2 * pr;
#pragma unroll
        for (int h = 0; h < 16; h++) {
            *reinterpret_cast<uint32_t*>(&akhi[base + h * 192]) = hh;
            *reinterpret_cast<uint32_t*>(&aklo[base + h * 192]) = ll;
        }
    }
}

// ================= HMMA flash attention (R9 exact shape) ====================
// BQ=64, BK=64, 128 threads (4 warps), warp = 16 q-rows x full 64 keys.
#define AQP 200
#define AVP 136
#define SM_QLO 12800
#define SM_ST  25600
#define STG_EL 43008
#define ATT_SMEM ((SM_ST + 2 * STG_EL) * 2)   // 223232 bytes

__global__ __launch_bounds__(128, 1) void attn_hmma(
    const bf16* __restrict__ qhi, const bf16* __restrict__ qlo,
    const bf16* __restrict__ khi, const bf16* __restrict__ klo,
    const bf16* __restrict__ vhi, const bf16* __restrict__ vlo,
    bf16* __restrict__ ohi, bf16* __restrict__ olo)
{
    extern __shared__ bf16 asmem[];
    const int qt = gridDim.x - 1 - blockIdx.x;    // long CTAs first
    const int h = blockIdx.y, b = blockIdx.z;
    const int tid = threadIdx.x, wid = tid >> 5, lane = tid & 31;
    const int q0 = qt * 64;
    const uint32_t sb = smem_u32(asmem);

    for (int i = tid; i < 1536; i += 128) {
        int r = i / 24, c = (i % 24) * 8;
        size_t g = ((size_t)(b * S_ + q0 + r) * H_ + h) * 192 + c;
        uint32_t d = sb + (r * AQP + c) * 2;
        cp_async16(d, qhi + g, 16);
        cp_async16(d + SM_QLO * 2, qlo + g, 16);
    }
    cp_commit();

    auto load_kv = [&](int kt, int s) {
        const int k0 = kt * 64;
        const uint32_t st = sb + (SM_ST + s * STG_EL) * 2;
        for (int i = tid; i < 1536; i += 128) {
            int r = i / 24, c = (i % 24) * 8;
            size_t g = ((size_t)(b * S_ + k0 + r) * H_ + h) * 192 + c;
            uint32_t d = st + (r * AQP + c) * 2;
            cp_async16(d, khi + g, 16);
            cp_async16(d + 12800 * 2, klo + g, 16);
        }
        for (int i = tid; i < 1024; i += 128) {
            int r = i / 16, c = (i % 16) * 8;
            size_t g = ((size_t)(b * S_ + k0 + r) * H_ + h) * 128 + c;
            uint32_t d = st + 25600 * 2 + (r * AVP + c) * 2;
            cp_async16(d, vhi + g, 16);
            cp_async16(d + 8704 * 2, vlo + g, 16);
        }
        cp_commit();
    };

    float oa[16][4];
#pragma unroll
    for (int j = 0; j < 16; j++)
#pragma unroll
        for (int e = 0; e < 4; e++) oa[j][e] = 0.f;
    float m0 = -1e30f, m1 = -1e30f, l0 = 0.f, l1 = 0.f;

    const int ntiles = qt + 1;
    load_kv(0, 0);

    const uint32_t qoff = sb + ((wid * 16 + (lane & 15)) * AQP + (lane >> 4) * 8) * 2;

    cp_wait<0>();
    __syncthreads();
    uint32_t qfh[12][4];
#pragma unroll
    for (int f = 0; f < 12; f++)
        ldmx4(qfh[f], qoff + f * 32);

    for (int kt = 0; kt < ntiles; kt++) {
        if (kt > 0) {
            cp_wait<0>();
            __syncthreads();
        }
        if (kt + 1 < ntiles) load_kv(kt + 1, (kt + 1) & 1);

        const uint32_t st = sb + (SM_ST + (kt & 1) * STG_EL) * 2;

        float c[8][4];
#pragma unroll
        for (int j = 0; j < 8; j++)
#pragma unroll
            for (int e = 0; e < 4; e++) c[j][e] = 0.f;

        const uint32_t kb = st + ((lane & 7) * AQP + (lane >> 3) * 8) * 2;
#pragma unroll
        for (int kp = 0; kp < 6; kp++) {
            uint32_t ql0[4], ql1[4];
            ldmx4(ql0, qoff + SM_QLO * 2 + kp * 64);
            ldmx4(ql1, qoff + SM_QLO * 2 + kp * 64 + 32);
#pragma unroll
            for (int nb = 0; nb < 8; nb++) {
                uint32_t kh[4], kl[4];
                ldmx4(kh, kb + nb * 8 * AQP * 2 + kp * 64);
                ldmx4(kl, kb + 12800 * 2 + nb * 8 * AQP * 2 + kp * 64);
                mma16816(c[nb], qfh[2*kp],   kh[0], kh[1]);
                mma16816(c[nb], qfh[2*kp+1], kh[2], kh[3]);
                mma16816(c[nb], qfh[2*kp],   kl[0], kl[1]);
                mma16816(c[nb], qfh[2*kp+1], kl[2], kl[3]);
                mma16816(c[nb], ql0, kh[0], kh[1]);
                mma16816(c[nb], ql1, kh[2], kh[3]);
            }
        }

        if (kt == qt) {
            const int r0 = wid * 16 + (lane >> 2);
            const int cbase = (lane & 3) * 2;
#pragma unroll
            for (int nb = 0; nb < 8; nb++) {
                int col = nb * 8 + cbase;
                if (col     > r0    ) c[nb][0] = -1e30f;
                if (col + 1 > r0    ) c[nb][1] = -1e30f;
                if (col     > r0 + 8) c[nb][2] = -1e30f;
                if (col + 1 > r0 + 8) c[nb][3] = -1e30f;
            }
        }

        float mx0 = -1e30f, mx1 = -1e30f;
#pragma unroll
        for (int nb = 0; nb < 8; nb++) {
            mx0 = fmaxf(mx0, fmaxf(c[nb][0], c[nb][1]));
            mx1 = fmaxf(mx1, fmaxf(c[nb][2], c[nb][3]));
        }
        mx0 = fmaxf(mx0, __shfl_xor_sync(0xffffffffu, mx0, 1));
        mx0 = fmaxf(mx0, __shfl_xor_sync(0xffffffffu, mx0, 2));
        mx1 = fmaxf(mx1, __shfl_xor_sync(0xffffffffu, mx1, 1));
        mx1 = fmaxf(mx1, __shfl_xor_sync(0xffffffffu, mx1, 2));
        float mn0 = fmaxf(m0, mx0), mn1 = fmaxf(m1, mx1);
        float co0 = __expf(m0 - mn0), co1 = __expf(m1 - mn1);
        m0 = mn0; m1 = mn1;
        float s0 = 0.f, s1 = 0.f;
#pragma unroll
        for (int nb = 0; nb < 8; nb++) {
            c[nb][0] = __expf(c[nb][0] - mn0); s0 += c[nb][0];
            c[nb][1] = __expf(c[nb][1] - mn0); s0 += c[nb][1];
            c[nb][2] = __expf(c[nb][2] - mn1); s1 += c[nb][2];
            c[nb][3] = __expf(c[nb][3] - mn1); s1 += c[nb][3];
        }
        s0 += __shfl_xor_sync(0xffffffffu, s0, 1);
        s0 += __shfl_xor_sync(0xffffffffu, s0, 2);
        s1 += __shfl_xor_sync(0xffffffffu, s1, 1);
        s1 += __shfl_xor_sync(0xffffffffu, s1, 2);
        l0 = l0 * co0 + s0;
        l1 = l1 * co1 + s1;
#pragma unroll
        for (int j = 0; j < 16; j++) {
            oa[j][0] *= co0; oa[j][1] *= co0;
            oa[j][2] *= co1; oa[j][3] *= co1;
        }

        const uint32_t vb = st + 25600 * 2 + ((lane & 15) * AVP + (lane >> 4) * 8) * 2;
#pragma unroll
        for (int kk = 0; kk < 4; kk++) {
            uint32_t ah[4], al[4];
            split2(c[2*kk][0],   c[2*kk][1],   ah[0], al[0]);
            split2(c[2*kk][2],   c[2*kk][3],   ah[1], al[1]);
            split2(c[2*kk+1][0], c[2*kk+1][1], ah[2], al[2]);
            split2(c[2*kk+1][2], c[2*kk+1][3], ah[3], al[3]);
#pragma unroll
            for (int n16 = 0; n16 < 8; n16++) {
                uint32_t vh[4], vl[4];
                ldmx4t(vh, vb + (kk * 16 * AVP + n16 * 16) * 2);
                ldmx4t(vl, vb + 8704 * 2 + (kk * 16 * AVP + n16 * 16) * 2);
                float* o0 = oa[2 * n16];
                float* o1 = oa[2 * n16 + 1];
                mma16816(o0, ah, vh[0], vh[1]);
                mma16816(o1, ah, vh[2], vh[3]);
                mma16816(o0, al, vh[0], vh[1]);
                mma16816(o1, al, vh[2], vh[3]);
                mma16816(o0, ah, vl[0], vl[1]);
                mma16816(o1, ah, vl[2], vl[3]);
            }
        }
    }

    const float i0 = 1.f / l0, i1 = 1.f / l1;
    const int r0 = q0 + wid * 16 + (lane >> 2);
    const size_t t0 = (size_t)(b * S_ + r0);
#pragma unroll
    for (int j = 0; j < 16; j++) {
        int col = h * 128 + j * 8 + (lane & 3) * 2;
        uint32_t hh, ll;
        split2(oa[j][0] * i0, oa[j][1] * i0, hh, ll);
        *reinterpret_cast<uint32_t*>(&ohi[t0 * (H_*DV_) + col]) = hh;
        *reinterpret_cast<uint32_t*>(&olo[t0 * (H_*DV_) + col]) = ll;
        split2(oa[j][2] * i1, oa[j][3] * i1, hh, ll);
        *reinterpret_cast<uint32_t*>(&ohi[(t0 + 8) * (H_*DV_) + col]) = hh;
        *reinterpret_cast<uint32_t*>(&olo[(t0 + 8) * (H_*DV_) + col]) = ll;
    }
}

// ---------------- launcher ----------------
extern "C" void kernel_launch(void* const* d_in, const int* in_sizes, int n_in,
                              void* d_out, int out_size)
{
    const float* x      = (const float*)d_in[0];
    const float* freqs  = (const float*)d_in[1];
    const float* wq_a   = (const float*)d_in[2];
    const float* q_an_w = (const float*)d_in[3];
    const float* wq_b   = (const float*)d_in[4];
    const float* wkv_a  = (const float*)d_in[5];
    const float* kv_n_w = (const float*)d_in[6];
    const float* wkv_b  = (const float*)d_in[7];
    const float* wo     = (const float*)d_in[8];
    float* out = (float*)d_out;

    float *qan, *kvall;
    cudaGetSymbolAddress((void**)&qan,   g_qan);
    cudaGetSymbolAddress((void**)&kvall, g_kvall);

    bf16 *xhi,*xlo,*qanhi,*qanlo,*kvnhi,*kvnlo,*athi,*atlo;
    bf16 *wqahi,*wqalo,*wqbhi,*wqblo,*wkvahi,*wkvalo,*wkvbhi,*wkvblo,*wohi,*wolo;
    bf16 *aqhi,*aqlo,*akhi,*aklo,*avhi,*avlo;
    cudaGetSymbolAddress((void**)&xhi, g_xhi);     cudaGetSymbolAddress((void**)&xlo, g_xlo);
    cudaGetSymbolAddress((void**)&qanhi, g_qanhi); cudaGetSymbolAddress((void**)&qanlo, g_qanlo);
    cudaGetSymbolAddress((void**)&kvnhi, g_kvnhi); cudaGetSymbolAddress((void**)&kvnlo, g_kvnlo);
    cudaGetSymbolAddress((void**)&athi, g_athi);   cudaGetSymbolAddress((void**)&atlo, g_atlo);
    cudaGetSymbolAddress((void**)&wqahi, g_wqahi); cudaGetSymbolAddress((void**)&wqalo, g_wqalo);
    cudaGetSymbolAddress((void**)&wqbhi, g_wqbhi); cudaGetSymbolAddress((void**)&wqblo, g_wqblo);
    cudaGetSymbolAddress((void**)&wkvahi, g_wkvahi); cudaGetSymbolAddress((void**)&wkvalo, g_wkvalo);
    cudaGetSymbolAddress((void**)&wkvbhi, g_wkvbhi); cudaGetSymbolAddress((void**)&wkvblo, g_wkvblo);
    cudaGetSymbolAddress((void**)&wohi, g_wohi);   cudaGetSymbolAddress((void**)&wolo, g_wolo);
    cudaGetSymbolAddress((void**)&aqhi, g_aqhi);   cudaGetSymbolAddress((void**)&aqlo, g_aqlo);
    cudaGetSymbolAddress((void**)&akhi, g_akhi);   cudaGetSymbolAddress((void**)&aklo, g_aklo);
    cudaGetSymbolAddress((void**)&avhi, g_avhi);   cudaGetSymbolAddress((void**)&avlo, g_avlo);

    cudaFuncSetAttribute(gemm_hmma, cudaFuncAttributeMaxDynamicSharedMemorySize, GSMEM);
    cudaFuncSetAttribute(attn_hmma, cudaFuncAttributeMaxDynamicSharedMemorySize, ATT_SMEM);

    // ---- merged input/weight converts ----
    CTab ct;
    const float* srcs[6] = {x, wq_a, wq_b, wkv_a, wkv_b, wo};
    bf16* his[6] = {xhi, wqahi, wqbhi, wkvahi, wkvbhi, wohi};
    bf16* los[6] = {xlo, wqalo, wqblo, wkvalo, wkvblo, wolo};
    size_t ns[6] = {(size_t)NT_*HID_, (size_t)QL_*HID_, (size_t)(H_*DQK_)*QL_,
                    (size_t)(KVL_+DR_)*HID_, (size_t)(H_*256)*KVL_, (size_t)HID_*(H_*DV_)};
    unsigned cum = 0;
    for (int i = 0; i < 6; i++) {
        ct.s[i] = srcs[i]; ct.h[i] = his[i]; ct.l[i] = los[i];
        ct.n4[i] = (unsigned)(ns[i] / 4);
        ct.start[i] = cum;
        cum += (ct.n4[i] + 255) / 256;
    }
    ct.start[6] = cum;
    convert_all<<<cum, 256>>>(ct);

    // ---- L1: wq_a + wkv_a (both read x planes) ----
    {
        Seg a = {xhi, xlo, wqahi, wqalo, qan, nullptr, nullptr, nullptr, nullptr,
                 freqs, QL_, HID_, QL_, QL_/128, 0};
        Seg b = {xhi, xlo, wkvahi, wkvalo, kvall, nullptr, nullptr, nullptr, nullptr,
                 freqs, KVL_+DR_, HID_, KVL_+DR_, (KVL_+DR_+127)/128, 0};
        int nb0 = (QL_/128) * (NT_/128);
        int nb1 = ((KVL_+DR_+127)/128) * (NT_/128);
        gemm_hmma<<<nb0 + nb1, 128, GSMEM>>>(a, b, nb0);
    }

    // ---- merged rmsnorms (+fused k_pe rope/broadcast) ----
    rmsnorm_both<<<2 * NT_, 256>>>(qan, q_an_w, qanhi, qanlo,
                                   kvall, kv_n_w, kvnhi, kvnlo,
                                   freqs, akhi, aklo);

    // ---- L2: wq_b (epi Q) + wkv_b (epi KV split) ----
    {
        Seg a = {qanhi, qanlo, wqbhi, wqblo, nullptr, aqhi, aqlo, nullptr, nullptr,
                 freqs, H_*DQK_, QL_, 0, (H_*DQK_)/128, 1};
        Seg b = {kvnhi, kvnlo, wkvbhi, wkvblo, nullptr, akhi, aklo, avhi, avlo,
                 freqs, H_*256, KVL_, 0, (H_*256)/128, 2};
        int nb0 = ((H_*DQK_)/128) * (NT_/128);
        int nb1 = ((H_*256)/128) * (NT_/128);
        gemm_hmma<<<nb0 + nb1, 128, GSMEM>>>(a, b, nb0);
    }

    // ---- attention (R9 exact shape) ----
    attn_hmma<<<dim3(S_ / 64, H_, B_), 128, ATT_SMEM>>>(
        aqhi, aqlo, akhi, aklo, avhi, avlo, athi, atlo);

    // ---- L3: wo ----
    {
        Seg a = {athi, atlo, wohi, wolo, out, nullptr, nullptr, nullptr, nullptr,
                 freqs, HID_, H_*DV_, HID_, HID_/128, 0};
        int nb0 = (HID_/128) * (NT_/128);
        gemm_hmma<<<nb0, 128, GSMEM>>>(a, a, nb0);
    }
}

// round 15
// speedup vs baseline: 1.5336x; 1.5336x over previous
#include <cuda_runtime.h>
#include <cuda_bf16.h>
#include <cstdint>

// ---------------- problem constants ----------------
#define B_   2
#define S_   2048
#define HID_ 2048
#define H_   16
#define QL_  1536
#define KVL_ 512
#define DN_  128
#define DR_  64
#define DV_  128
#define DQK_ 192
#define NT_  (B_*S_)        // 4096 tokens

typedef __nv_bfloat16 bf16;

// ---------------- scratch (static device globals; no alloc) ----------------
__device__ __align__(128) float g_qan[(size_t)NT_ * QL_];
__device__ __align__(128) float g_kvall[(size_t)NT_ * (KVL_ + DR_)];

__device__ __align__(128) bf16 g_xhi[(size_t)NT_ * HID_],  g_xlo[(size_t)NT_ * HID_];
__device__ __align__(128) bf16 g_qanhi[(size_t)NT_ * QL_], g_qanlo[(size_t)NT_ * QL_];
__device__ __align__(128) bf16 g_kvnhi[(size_t)NT_ * KVL_],g_kvnlo[(size_t)NT_ * KVL_];
__device__ __align__(128) bf16 g_athi[(size_t)NT_ * (H_*DV_)], g_atlo[(size_t)NT_ * (H_*DV_)];
__device__ __align__(128) bf16 g_wqahi[(size_t)QL_ * HID_],        g_wqalo[(size_t)QL_ * HID_];
__device__ __align__(128) bf16 g_wqbhi[(size_t)(H_*DQK_) * QL_],   g_wqblo[(size_t)(H_*DQK_) * QL_];
__device__ __align__(128) bf16 g_wkvahi[(size_t)(KVL_+DR_) * HID_],g_wkvalo[(size_t)(KVL_+DR_) * HID_];
__device__ __align__(128) bf16 g_wkvbhi[(size_t)(H_*256) * KVL_],  g_wkvblo[(size_t)(H_*256) * KVL_];
__device__ __align__(128) bf16 g_wohi[(size_t)HID_ * (H_*DV_)],    g_wolo[(size_t)HID_ * (H_*DV_)];

// attention operand planes, packed per head
__device__ __align__(128) bf16 g_aqhi[(size_t)NT_ * H_ * DQK_], g_aqlo[(size_t)NT_ * H_ * DQK_];
__device__ __align__(128) bf16 g_akhi[(size_t)NT_ * H_ * DQK_], g_aklo[(size_t)NT_ * H_ * DQK_];
__device__ __align__(128) bf16 g_avhi[(size_t)NT_ * H_ * DV_],  g_avlo[(size_t)NT_ * H_ * DV_];

// ================= PTX helpers (baseline compute_103 features only) =========
__device__ __forceinline__ uint32_t smem_u32(const void* p) {
    uint32_t a;
    asm("{ .reg .u64 t; cvta.to.shared.u64 t, %1; cvt.u32.u64 %0, t; }" : "=r"(a) : "l"(p));
    return a;
}
__device__ __forceinline__ void cp_async16(uint32_t dst, const void* src, int src_bytes) {
    asm volatile("cp.async.cg.shared.global [%0], [%1], 16, %2;"
                 :: "r"(dst), "l"(src), "r"(src_bytes) : "memory");
}
__device__ __forceinline__ void cp_commit() {
    asm volatile("cp.async.commit_group;" ::: "memory");
}
template <int N>
__device__ __forceinline__ void cp_wait() {
    asm volatile("cp.async.wait_group %0;" :: "n"(N) : "memory");
}
__device__ __forceinline__ void ldmx4(uint32_t* r, uint32_t addr) {
    asm volatile("ldmatrix.sync.aligned.m8n8.x4.shared.b16 {%0,%1,%2,%3}, [%4];"
                 : "=r"(r[0]), "=r"(r[1]), "=r"(r[2]), "=r"(r[3]) : "r"(addr));
}
__device__ __forceinline__ void ldmx2(uint32_t* r, uint32_t addr) {
    asm volatile("ldmatrix.sync.aligned.m8n8.x2.shared.b16 {%0,%1}, [%2];"
                 : "=r"(r[0]), "=r"(r[1]) : "r"(addr));
}
__device__ __forceinline__ void ldmx4t(uint32_t* r, uint32_t addr) {
    asm volatile("ldmatrix.sync.aligned.m8n8.x4.trans.shared.b16 {%0,%1,%2,%3}, [%4];"
                 : "=r"(r[0]), "=r"(r[1]), "=r"(r[2]), "=r"(r[3]) : "r"(addr));
}
__device__ __forceinline__ void mma16816(float* c, const uint32_t* a, uint32_t b0, uint32_t b1) {
    asm("mma.sync.aligned.m16n8k16.row.col.f32.bf16.bf16.f32 "
        "{%0,%1,%2,%3}, {%4,%5,%6,%7}, {%8,%9}, {%0,%1,%2,%3};"
        : "+f"(c[0]), "+f"(c[1]), "+f"(c[2]), "+f"(c[3])
        : "r"(a[0]), "r"(a[1]), "r"(a[2]), "r"(a[3]), "r"(b0), "r"(b1));
}
__device__ __forceinline__ uint32_t packbf(float x, float y) {
    uint32_t r;
    asm("cvt.rn.bf16x2.f32 %0, %1, %2;" : "=r"(r) : "f"(y), "f"(x));
    return r;
}
__device__ __forceinline__ void split2(float x, float y, uint32_t& hi, uint32_t& lo) {
    float xh = __bfloat162float(__float2bfloat16(x));
    float yh = __bfloat162float(__float2bfloat16(y));
    hi = packbf(xh, yh);
    lo = packbf(x - xh, y - yh);
}

// ================= HMMA split-bf16 GEMM (R13 validated optimum) ==============
// CTA tile 128x128, 4 warps (128 thr) of 64x64, 2 CTAs/SM, 2-stage pipeline.
#define GBK 32
#define ROWB 80
#define APL 10240                  // plane: 128 rows * 80B
#define GBUF (4 * APL)             // Ah,Al,Bh,Bl = 40960 B per stage
#define GSMEM (2 * GBUF)           // 81920 B

struct Seg {
    const bf16 *Ah, *Al, *Wh, *Wl;
    float* C;
    bf16 *P1, *P2, *P3, *P4;
    const float* fc;
    int N, K, ldc, gx, epi;   // epi: 0=fp32 C, 1=Q(scale+rope+split), 2=KV split
};

__device__ __forceinline__ void load_tile(
    const bf16* __restrict__ g, int ld, int rowbase, int rowlim,
    int kcol, uint32_t sdst, int tid)
{
#pragma unroll
    for (int i = 0; i < 4; ++i) {
        int idx = tid + i * 128;
        int r = idx >> 2;
        int c8 = (idx & 3) << 3;
        int gr = rowbase + r;
        int ok = (gr < rowlim);
        const bf16* src = g + (size_t)(ok ? gr : rowbase) * ld + kcol + c8;
        cp_async16(sdst + r * ROWB + c8 * 2, src, ok ? 16 : 0);
    }
}

extern __shared__ uint8_t dsm[];

__global__ __launch_bounds__(128, 2) void gemm_hmma(Seg s0, Seg s1, int nb0)
{
    const Seg s = (blockIdx.x < (unsigned)nb0) ? s0 : s1;
    const int bid = (blockIdx.x < (unsigned)nb0) ? blockIdx.x : blockIdx.x - nb0;
    const int tid  = threadIdx.x;
    const int wid  = tid >> 5;
    const int lane = tid & 31;
    const int bm = (bid / s.gx) * 128;
    const int bn = (bid % s.gx) * 128;
    const int wm = (wid & 1) * 64;        // 2 warps in M
    const int wn = (wid >> 1) * 64;       // 2 warps in N
    const uint32_t sb = smem_u32(dsm);

    float acc[4][8][4];
#pragma unroll
    for (int i = 0; i < 4; i++)
#pragma unroll
        for (int j = 0; j < 8; j++)
#pragma unroll
            for (int k = 0; k < 4; k++) acc[i][j][k] = 0.f;

    const int nchunks = s.K / GBK;

    {
        uint32_t buf = sb;
        load_tile(s.Ah, s.K, bm, 1 << 30, 0, buf,           tid);
        load_tile(s.Al, s.K, bm, 1 << 30, 0, buf + APL,     tid);
        load_tile(s.Wh, s.K, bn, s.N,     0, buf + 2 * APL, tid);
        load_tile(s.Wl, s.K, bn, s.N,     0, buf + 3 * APL, tid);
        cp_commit();
    }

    const uint32_t a_off = (uint32_t)((wm + (lane & 15)) * ROWB + ((lane >> 4) << 3) * 2);
    const uint32_t b_off = (uint32_t)((wn + (lane & 7)) * ROWB + ((lane >> 3) & 1) * 16);

    for (int c = 0; c < nchunks; ++c) {
        cp_wait<0>();
        __syncthreads();              // single barrier per chunk

        if (c + 1 < nchunks) {
            uint32_t buf = sb + ((c + 1) & 1) * GBUF;
            int kcol = (c + 1) * GBK;
            load_tile(s.Ah, s.K, bm, 1 << 30, kcol, buf,           tid);
            load_tile(s.Al, s.K, bm, 1 << 30, kcol, buf + APL,     tid);
            load_tile(s.Wh, s.K, bn, s.N,     kcol, buf + 2 * APL, tid);
            load_tile(s.Wl, s.K, bn, s.N,     kcol, buf + 3 * APL, tid);
            cp_commit();
        }

        const uint32_t buf = sb + (c & 1) * GBUF;

#pragma unroll
        for (int kf = 0; kf < 2; ++kf) {
            uint32_t afr[2][4][4];
#pragma unroll
            for (int pl = 0; pl < 2; ++pl)
#pragma unroll
                for (int mi = 0; mi < 4; ++mi)
                    ldmx4(afr[pl][mi],
                          buf + pl * APL + a_off + mi * 16 * ROWB + kf * 32);
#pragma unroll
            for (int ni = 0; ni < 8; ++ni) {
                uint32_t bh[2], bl[2];
                ldmx2(bh, buf + 2 * APL + b_off + ni * 8 * ROWB + kf * 32);
                ldmx2(bl, buf + 3 * APL + b_off + ni * 8 * ROWB + kf * 32);
#pragma unroll
                for (int mi = 0; mi < 4; ++mi) {
                    float* d = acc[mi][ni];
                    mma16816(d, afr[0][mi], bh[0], bh[1]);   // hi*hi
                    mma16816(d, afr[0][mi], bl[0], bl[1]);   // hi*lo
                    mma16816(d, afr[1][mi], bh[0], bh[1]);   // lo*hi
                }
            }
        }
    }

    // -------- epilogues --------
    const int r0 = bm + wm + (lane >> 2);
    const int cb = bn + wn + (lane & 3) * 2;

    if (s.epi == 0) {
#pragma unroll
        for (int mi = 0; mi < 4; ++mi)
#pragma unroll
            for (int ni = 0; ni < 8; ++ni) {
                int col = cb + ni * 8;
                if (col < s.N) {
                    int row = r0 + mi * 16;
                    *reinterpret_cast<float2*>(&s.C[(size_t)row * s.ldc + col]) =
                        make_float2(acc[mi][ni][0], acc[mi][ni][1]);
                    *reinterpret_cast<float2*>(&s.C[(size_t)(row + 8) * s.ldc + col]) =
                        make_float2(acc[mi][ni][2], acc[mi][ni][3]);
                }
            }
    } else if (s.epi == 1) {
        const float sc = 0.07216878364870323f;   // 1/sqrt(192)
#pragma unroll
        for (int mi = 0; mi < 4; ++mi)
#pragma unroll
            for (int ni = 0; ni < 8; ++ni) {
                int col = cb + ni * 8;
                int row = r0 + mi * 16;
                int d = col % 192;
                float a0 = acc[mi][ni][0], a1 = acc[mi][ni][1];
                float a2 = acc[mi][ni][2], a3 = acc[mi][ni][3];
                if (d >= 128) {
                    int p = (d - 128) >> 1;
                    int sA = row & (S_ - 1), sB = (row + 8) & (S_ - 1);
                    float cA = s.fc[(sA * 32 + p) * 2], snA = s.fc[(sA * 32 + p) * 2 + 1];
                    float cB = s.fc[(sB * 32 + p) * 2], snB = s.fc[(sB * 32 + p) * 2 + 1];
                    float t0 = a0 * cA - a1 * snA, t1 = a0 * snA + a1 * cA;
                    float t2 = a2 * cB - a3 * snB, t3 = a2 * snB + a3 * cB;
                    a0 = t0; a1 = t1; a2 = t2; a3 = t3;
                }
                a0 *= sc; a1 *= sc; a2 *= sc; a3 *= sc;
                uint32_t hh, ll;
                split2(a0, a1, hh, ll);
                *reinterpret_cast<uint32_t*>(&s.P1[(size_t)row * 3072 + col]) = hh;
                *reinterpret_cast<uint32_t*>(&s.P2[(size_t)row * 3072 + col]) = ll;
                split2(a2, a3, hh, ll);
                *reinterpret_cast<uint32_t*>(&s.P1[(size_t)(row + 8) * 3072 + col]) = hh;
                *reinterpret_cast<uint32_t*>(&s.P2[(size_t)(row + 8) * 3072 + col]) = ll;
            }
    } else {
#pragma unroll
        for (int mi = 0; mi < 4; ++mi)
#pragma unroll
            for (int ni = 0; ni < 8; ++ni) {
                int col = cb + ni * 8;
                int row = r0 + mi * 16;
                int h = col >> 8, d = col & 255;
                bf16 *H, *L;
                size_t idx; size_t st;
                if (d < 128) { idx = ((size_t)row * 16 + h) * 192 + d;        st = (size_t)8 * 16 * 192; H = s.P1; L = s.P2; }
                else         { idx = ((size_t)row * 16 + h) * 128 + (d - 128); st = (size_t)8 * 16 * 128; H = s.P3; L = s.P4; }
                uint32_t hh, ll;
                split2(acc[mi][ni][0], acc[mi][ni][1], hh, ll);
                *reinterpret_cast<uint32_t*>(&H[idx]) = hh;
                *reinterpret_cast<uint32_t*>(&L[idx]) = ll;
                split2(acc[mi][ni][2], acc[mi][ni][3], hh, ll);
                *reinterpret_cast<uint32_t*>(&H[idx + st]) = hh;
                *reinterpret_cast<uint32_t*>(&L[idx + st]) = ll;
            }
    }
}

// ================= converts (single merged launch) =================
struct CTab {
    const float* s[6];
    bf16 *h[6], *l[6];
    unsigned n4[6];
    unsigned start[7];
};

__global__ void convert_all(CTab t)
{
    unsigned b = blockIdx.x;
    int k = 0;
#pragma unroll
    for (int j = 1; j < 6; j++) if (b >= t.start[j]) k = j;
    size_t i = (size_t)(b - t.start[k]) * 256 + threadIdx.x;
    if (i >= t.n4[k]) return;
    float4 v = reinterpret_cast<const float4*>(t.s[k])[i];
    bf16 h0 = __float2bfloat16(v.x), h1 = __float2bfloat16(v.y);
    bf16 h2 = __float2bfloat16(v.z), h3 = __float2bfloat16(v.w);
    bf16 l0 = __float2bfloat16(v.x - __bfloat162float(h0));
    bf16 l1 = __float2bfloat16(v.y - __bfloat162float(h1));
    bf16 l2 = __float2bfloat16(v.z - __bfloat162float(h2));
    bf16 l3 = __float2bfloat16(v.w - __bfloat162float(h3));
    __nv_bfloat162* hp = reinterpret_cast<__nv_bfloat162*>(t.h[k]);
    __nv_bfloat162* lp = reinterpret_cast<__nv_bfloat162*>(t.l[k]);
    hp[2*i]   = __nv_bfloat162(h0, h1); hp[2*i+1] = __nv_bfloat162(h2, h3);
    lp[2*i]   = __nv_bfloat162(l0, l1); lp[2*i+1] = __nv_bfloat162(l2, l3);
}

// ---------- merged RMSNorm(q) + RMSNorm(kv) + k_pe rope/broadcast ----------
__global__ void rmsnorm_both(
    const float* __restrict__ qan, const float* __restrict__ qw,
    bf16* __restrict__ qhi, bf16* __restrict__ qlo,
    const float* __restrict__ kvall, const float* __restrict__ kvw,
    bf16* __restrict__ kvhi, bf16* __restrict__ kvlo,
    const float* __restrict__ fc,
    bf16* __restrict__ akhi, bf16* __restrict__ aklo)
{
    __shared__ float red[256];
    const int blk = blockIdx.x;
    const int isq = (blk < NT_);
    const int row = isq ? blk : blk - NT_;
    const int n = isq ? QL_ : KVL_;
    const float* p = isq ? qan + (size_t)row * QL_
                         : kvall + (size_t)row * (KVL_ + DR_);
    const float* w = isq ? qw : kvw;
    bf16* hi = isq ? qhi : kvhi;
    bf16* lo = isq ? qlo : kvlo;

    float sacc = 0.f;
    for (int i = threadIdx.x; i < n; i += 256) { float v = p[i]; sacc += v * v; }
    red[threadIdx.x] = sacc;
    __syncthreads();
    for (int o = 128; o > 0; o >>= 1) {
        if (threadIdx.x < o) red[threadIdx.x] += red[threadIdx.x + o];
        __syncthreads();
    }
    float inv = rsqrtf(red[0] / n + 1e-6f);
    for (int i = threadIdx.x * 2; i < n; i += 512) {
        float v0 = p[i] * inv * w[i];
        float v1 = p[i + 1] * inv * w[i + 1];
        uint32_t hh, ll;
        split2(v0, v1, hh, ll);
        *reinterpret_cast<uint32_t*>(&hi[(size_t)row * n + i]) = hh;
        *reinterpret_cast<uint32_t*>(&lo[(size_t)row * n + i]) = ll;
    }

    if (!isq && threadIdx.x < 32) {
        const int pr = threadIdx.x;
        const int sfx = row & (S_ - 1);
        float xr = p[KVL_ + 2 * pr];
        float xi = p[KVL_ + 2 * pr + 1];
        float c = fc[(sfx * 32 + pr) * 2], sn = fc[(sfx * 32 + pr) * 2 + 1];
        float r0 = xr * c - xi * sn, r1 = xr * sn + xi * c;
        uint32_t hh, ll;
        split2(r0, r1, hh, ll);
        size_t base = ((size_t)row * 16) * 192 + 128 + 2 * pr;
#pragma unroll
        for (int h = 0; h < 16; h++) {
            *reinterpret_cast<uint32_t*>(&akhi[base + h * 192]) = hh;
            *reinterpret_cast<uint32_t*>(&aklo[base + h * 192]) = ll;
        }
    }
}

// ================= HMMA flash attention (R9 exact shape) ====================
// BQ=64, BK=64, 128 threads (4 warps), warp = 16 q-rows x full 64 keys.
#define AQP 200
#define AVP 136
#define SM_QLO 12800
#define SM_ST  25600
#define STG_EL 43008
#define ATT_SMEM ((SM_ST + 2 * STG_EL) * 2)   // 223232 bytes

__global__ __launch_bounds__(128, 1) void attn_hmma(
    const bf16* __restrict__ qhi, const bf16* __restrict__ qlo,
    const bf16* __restrict__ khi, const bf16* __restrict__ klo,
    const bf16* __restrict__ vhi, const bf16* __restrict__ vlo,
    bf16* __restrict__ ohi, bf16* __restrict__ olo)
{
    extern __shared__ bf16 asmem[];
    const int qt = gridDim.x - 1 - blockIdx.x;    // long CTAs first
    const int h = blockIdx.y, b = blockIdx.z;
    const int tid = threadIdx.x, wid = tid >> 5, lane = tid & 31;
    const int q0 = qt * 64;
    const uint32_t sb = smem_u32(asmem);

    for (int i = tid; i < 1536; i += 128) {
        int r = i / 24, c = (i % 24) * 8;
        size_t g = ((size_t)(b * S_ + q0 + r) * H_ + h) * 192 + c;
        uint32_t d = sb + (r * AQP + c) * 2;
        cp_async16(d, qhi + g, 16);
        cp_async16(d + SM_QLO * 2, qlo + g, 16);
    }
    cp_commit();

    auto load_kv = [&](int kt, int s) {
        const int k0 = kt * 64;
        const uint32_t st = sb + (SM_ST + s * STG_EL) * 2;
        for (int i = tid; i < 1536; i += 128) {
            int r = i / 24, c = (i % 24) * 8;
            size_t g = ((size_t)(b * S_ + k0 + r) * H_ + h) * 192 + c;
            uint32_t d = st + (r * AQP + c) * 2;
            cp_async16(d, khi + g, 16);
            cp_async16(d + 12800 * 2, klo + g, 16);
        }
        for (int i = tid; i < 1024; i += 128) {
            int r = i / 16, c = (i % 16) * 8;
            size_t g = ((size_t)(b * S_ + k0 + r) * H_ + h) * 128 + c;
            uint32_t d = st + 25600 * 2 + (r * AVP + c) * 2;
            cp_async16(d, vhi + g, 16);
            cp_async16(d + 8704 * 2, vlo + g, 16);
        }
        cp_commit();
    };

    float oa[16][4];
#pragma unroll
    for (int j = 0; j < 16; j++)
#pragma unroll
        for (int e = 0; e < 4; e++) oa[j][e] = 0.f;
    float m0 = -1e30f, m1 = -1e30f, l0 = 0.f, l1 = 0.f;

    const int ntiles = qt + 1;
    load_kv(0, 0);

    const uint32_t qoff = sb + ((wid * 16 + (lane & 15)) * AQP + (lane >> 4) * 8) * 2;

    cp_wait<0>();
    __syncthreads();
    uint32_t qfh[12][4];
#pragma unroll
    for (int f = 0; f < 12; f++)
        ldmx4(qfh[f], qoff + f * 32);

    for (int kt = 0; kt < ntiles; kt++) {
        if (kt > 0) {
            cp_wait<0>();
            __syncthreads();
        }
        if (kt + 1 < ntiles) load_kv(kt + 1, (kt + 1) & 1);

        const uint32_t st = sb + (SM_ST + (kt & 1) * STG_EL) * 2;

        float c[8][4];
#pragma unroll
        for (int j = 0; j < 8; j++)
#pragma unroll
            for (int e = 0; e < 4; e++) c[j][e] = 0.f;

        const uint32_t kb = st + ((lane & 7) * AQP + (lane >> 3) * 8) * 2;
#pragma unroll
        for (int kp = 0; kp < 6; kp++) {
            uint32_t ql0[4], ql1[4];
            ldmx4(ql0, qoff + SM_QLO * 2 + kp * 64);
            ldmx4(ql1, qoff + SM_QLO * 2 + kp * 64 + 32);
#pragma unroll
            for (int nb = 0; nb < 8; nb++) {
                uint32_t kh[4], kl[4];
                ldmx4(kh, kb + nb * 8 * AQP * 2 + kp * 64);
                ldmx4(kl, kb + 12800 * 2 + nb * 8 * AQP * 2 + kp * 64);
                mma16816(c[nb], qfh[2*kp],   kh[0], kh[1]);
                mma16816(c[nb], qfh[2*kp+1], kh[2], kh[3]);
                mma16816(c[nb], qfh[2*kp],   kl[0], kl[1]);
                mma16816(c[nb], qfh[2*kp+1], kl[2], kl[3]);
                mma16816(c[nb], ql0, kh[0], kh[1]);
                mma16816(c[nb], ql1, kh[2], kh[3]);
            }
        }

        if (kt == qt) {
            const int r0 = wid * 16 + (lane >> 2);
            const int cbase = (lane & 3) * 2;
#pragma unroll
            for (int nb = 0; nb < 8; nb++) {
                int col = nb * 8 + cbase;
                if (col     > r0    ) c[nb][0] = -1e30f;
                if (col + 1 > r0    ) c[nb][1] = -1e30f;
                if (col     > r0 + 8) c[nb][2] = -1e30f;
                if (col + 1 > r0 + 8) c[nb][3] = -1e30f;
            }
        }

        float mx0 = -1e30f, mx1 = -1e30f;
#pragma unroll
        for (int nb = 0; nb < 8; nb++) {
            mx0 = fmaxf(mx0, fmaxf(c[nb][0], c[nb][1]));
            mx1 = fmaxf(mx1, fmaxf(c[nb][2], c[nb][3]));
        }
        mx0 = fmaxf(mx0, __shfl_xor_sync(0xffffffffu, mx0, 1));
        mx0 = fmaxf(mx0, __shfl_xor_sync(0xffffffffu, mx0, 2));
        mx1 = fmaxf(mx1, __shfl_xor_sync(0xffffffffu, mx1, 1));
        mx1 = fmaxf(mx1, __shfl_xor_sync(0xffffffffu, mx1, 2));
        float mn0 = fmaxf(m0, mx0), mn1 = fmaxf(m1, mx1);
        float co0 = __expf(m0 - mn0), co1 = __expf(m1 - mn1);
        m0 = mn0; m1 = mn1;
        float s0 = 0.f, s1 = 0.f;
#pragma unroll
        for (int nb = 0; nb < 8; nb++) {
            c[nb][0] = __expf(c[nb][0] - mn0); s0 += c[nb][0];
            c[nb][1] = __expf(c[nb][1] - mn0); s0 += c[nb][1];
            c[nb][2] = __expf(c[nb][2] - mn1); s1 += c[nb][2];
            c[nb][3] = __expf(c[nb][3] - mn1); s1 += c[nb][3];
        }
        s0 += __shfl_xor_sync(0xffffffffu, s0, 1);
        s0 += __shfl_xor_sync(0xffffffffu, s0, 2);
        s1 += __shfl_xor_sync(0xffffffffu, s1, 1);
        s1 += __shfl_xor_sync(0xffffffffu, s1, 2);
        l0 = l0 * co0 + s0;
        l1 = l1 * co1 + s1;
#pragma unroll
        for (int j = 0; j < 16; j++) {
            oa[j][0] *= co0; oa[j][1] *= co0;
            oa[j][2] *= co1; oa[j][3] *= co1;
        }

        const uint32_t vb = st + 25600 * 2 + ((lane & 15) * AVP + (lane >> 4) * 8) * 2;
#pragma unroll
        for (int kk = 0; kk < 4; kk++) {
            uint32_t ah[4], al[4];
            split2(c[2*kk][0],   c[2*kk][1],   ah[0], al[0]);
            split2(c[2*kk][2],   c[2*kk][3],   ah[1], al[1]);
            split2(c[2*kk+1][0], c[2*kk+1][1], ah[2], al[2]);
            split2(c[2*kk+1][2], c[2*kk+1][3], ah[3], al[3]);
#pragma unroll
            for (int n16 = 0; n16 < 8; n16++) {
                uint32_t vh[4], vl[4];
                ldmx4t(vh, vb + (kk * 16 * AVP + n16 * 16) * 2);
                ldmx4t(vl, vb + 8704 * 2 + (kk * 16 * AVP + n16 * 16) * 2);
                float* o0 = oa[2 * n16];
                float* o1 = oa[2 * n16 + 1];
                mma16816(o0, ah, vh[0], vh[1]);
                mma16816(o1, ah, vh[2], vh[3]);
                mma16816(o0, al, vh[0], vh[1]);
                mma16816(o1, al, vh[2], vh[3]);
                mma16816(o0, ah, vl[0], vl[1]);
                mma16816(o1, ah, vl[2], vl[3]);
            }
        }
    }

    const float i0 = 1.f / l0, i1 = 1.f / l1;
    const int r0 = q0 + wid * 16 + (lane >> 2);
    const size_t t0 = (size_t)(b * S_ + r0);
#pragma unroll
    for (int j = 0; j < 16; j++) {
        int col = h * 128 + j * 8 + (lane & 3) * 2;
        uint32_t hh, ll;
        split2(oa[j][0] * i0, oa[j][1] * i0, hh, ll);
        *reinterpret_cast<uint32_t*>(&ohi[t0 * (H_*DV_) + col]) = hh;
        *reinterpret_cast<uint32_t*>(&olo[t0 * (H_*DV_) + col]) = ll;
        split2(oa[j][2] * i1, oa[j][3] * i1, hh, ll);
        *reinterpret_cast<uint32_t*>(&ohi[(t0 + 8) * (H_*DV_) + col]) = hh;
        *reinterpret_cast<uint32_t*>(&olo[(t0 + 8) * (H_*DV_) + col]) = ll;
    }
}

// ---------------- launcher ----------------
extern "C" void kernel_launch(void* const* d_in, const int* in_sizes, int n_in,
                              void* d_out, int out_size)
{
    const float* x      = (const float*)d_in[0];
    const float* freqs  = (const float*)d_in[1];
    const float* wq_a   = (const float*)d_in[2];
    const float* q_an_w = (const float*)d_in[3];
    const float* wq_b   = (const float*)d_in[4];
    const float* wkv_a  = (const float*)d_in[5];
    const float* kv_n_w = (const float*)d_in[6];
    const float* wkv_b  = (const float*)d_in[7];
    const float* wo     = (const float*)d_in[8];
    float* out = (float*)d_out;

    float *qan, *kvall;
    cudaGetSymbolAddress((void**)&qan,   g_qan);
    cudaGetSymbolAddress((void**)&kvall, g_kvall);

    bf16 *xhi,*xlo,*qanhi,*qanlo,*kvnhi,*kvnlo,*athi,*atlo;
    bf16 *wqahi,*wqalo,*wqbhi,*wqblo,*wkvahi,*wkvalo,*wkvbhi,*wkvblo,*wohi,*wolo;
    bf16 *aqhi,*aqlo,*akhi,*aklo,*avhi,*avlo;
    cudaGetSymbolAddress((void**)&xhi, g_xhi);     cudaGetSymbolAddress((void**)&xlo, g_xlo);
    cudaGetSymbolAddress((void**)&qanhi, g_qanhi); cudaGetSymbolAddress((void**)&qanlo, g_qanlo);
    cudaGetSymbolAddress((void**)&kvnhi, g_kvnhi); cudaGetSymbolAddress((void**)&kvnlo, g_kvnlo);
    cudaGetSymbolAddress((void**)&athi, g_athi);   cudaGetSymbolAddress((void**)&atlo, g_atlo);
    cudaGetSymbolAddress((void**)&wqahi, g_wqahi); cudaGetSymbolAddress((void**)&wqalo, g_wqalo);
    cudaGetSymbolAddress((void**)&wqbhi, g_wqbhi); cudaGetSymbolAddress((void**)&wqblo, g_wqblo);
    cudaGetSymbolAddress((void**)&wkvahi, g_wkvahi); cudaGetSymbolAddress((void**)&wkvalo, g_wkvalo);
    cudaGetSymbolAddress((void**)&wkvbhi, g_wkvbhi); cudaGetSymbolAddress((void**)&wkvblo, g_wkvblo);
    cudaGetSymbolAddress((void**)&wohi, g_wohi);   cudaGetSymbolAddress((void**)&wolo, g_wolo);
    cudaGetSymbolAddress((void**)&aqhi, g_aqhi);   cudaGetSymbolAddress((void**)&aqlo, g_aqlo);
    cudaGetSymbolAddress((void**)&akhi, g_akhi);   cudaGetSymbolAddress((void**)&aklo, g_aklo);
    cudaGetSymbolAddress((void**)&avhi, g_avhi);   cudaGetSymbolAddress((void**)&avlo, g_avlo);

    cudaFuncSetAttribute(gemm_hmma, cudaFuncAttributeMaxDynamicSharedMemorySize, GSMEM);
    cudaFuncSetAttribute(attn_hmma, cudaFuncAttributeMaxDynamicSharedMemorySize, ATT_SMEM);

    // ---- merged input/weight converts ----
    CTab ct;
    const float* srcs[6] = {x, wq_a, wq_b, wkv_a, wkv_b, wo};
    bf16* his[6] = {xhi, wqahi, wqbhi, wkvahi, wkvbhi, wohi};
    bf16* los[6] = {xlo, wqalo, wqblo, wkvalo, wkvblo, wolo};
    size_t ns[6] = {(size_t)NT_*HID_, (size_t)QL_*HID_, (size_t)(H_*DQK_)*QL_,
                    (size_t)(KVL_+DR_)*HID_, (size_t)(H_*256)*KVL_, (size_t)HID_*(H_*DV_)};
    unsigned cum = 0;
    for (int i = 0; i < 6; i++) {
        ct.s[i] = srcs[i]; ct.h[i] = his[i]; ct.l[i] = los[i];
        ct.n4[i] = (unsigned)(ns[i] / 4);
        ct.start[i] = cum;
        cum += (ct.n4[i] + 255) / 256;
    }
    ct.start[6] = cum;
    convert_all<<<cum, 256>>>(ct);

    // ---- L1: wq_a + wkv_a (both read x planes) ----
    {
        Seg a = {xhi, xlo, wqahi, wqalo, qan, nullptr, nullptr, nullptr, nullptr,
                 freqs, QL_, HID_, QL_, QL_/128, 0};
        Seg b = {xhi, xlo, wkvahi, wkvalo, kvall, nullptr, nullptr, nullptr, nullptr,
                 freqs, KVL_+DR_, HID_, KVL_+DR_, (KVL_+DR_+127)/128, 0};
        int nb0 = (QL_/128) * (NT_/128);
        int nb1 = ((KVL_+DR_+127)/128) * (NT_/128);
        gemm_hmma<<<nb0 + nb1, 128, GSMEM>>>(a, b, nb0);
    }

    // ---- merged rmsnorms (+fused k_pe rope/broadcast) ----
    rmsnorm_both<<<2 * NT_, 256>>>(qan, q_an_w, qanhi, qanlo,
                                   kvall, kv_n_w, kvnhi, kvnlo,
                                   freqs, akhi, aklo);

    // ---- L2: wq_b (epi Q) + wkv_b (epi KV split) ----
    {
        Seg a = {qanhi, qanlo, wqbhi, wqblo, nullptr, aqhi, aqlo, nullptr, nullptr,
                 freqs, H_*DQK_, QL_, 0, (H_*DQK_)/128, 1};
        Seg b = {kvnhi, kvnlo, wkvbhi, wkvblo, nullptr, akhi, aklo, avhi, avlo,
                 freqs, H_*256, KVL_, 0, (H_*256)/128, 2};
        int nb0 = ((H_*DQK_)/128) * (NT_/128);
        int nb1 = ((H_*256)/128) * (NT_/128);
        gemm_hmma<<<nb0 + nb1, 128, GSMEM>>>(a, b, nb0);
    }

    // ---- attention (R9 exact shape) ----
    attn_hmma<<<dim3(S_ / 64, H_, B_), 128, ATT_SMEM>>>(
        aqhi, aqlo, akhi, aklo, avhi, avlo, athi, atlo);

    // ---- L3: wo ----
    {
        Seg a = {athi, atlo, wohi, wolo, out, nullptr, nullptr, nullptr, nullptr,
                 freqs, HID_, H_*DV_, HID_, HID_/128, 0};
        int nb0 = (HID_/128) * (NT_/128);
        gemm_hmma<<<nb0, 128, GSMEM>>>(a, a, nb0);
    }
}

// round 16
// speedup vs baseline: 1.5362x; 1.0017x over previous
#include <cuda_runtime.h>
#include <cuda_bf16.h>
#include <cstdint>

// ---------------- problem constants ----------------
#define B_   2
#define S_   2048
#define HID_ 2048
#define H_   16
#define QL_  1536
#define KVL_ 512
#define DN_  128
#define DR_  64
#define DV_  128
#define DQK_ 192
#define NT_  (B_*S_)        // 4096 tokens

typedef __nv_bfloat16 bf16;

// ---------------- scratch (static device globals; no alloc) ----------------
__device__ __align__(128) float g_qan[(size_t)NT_ * QL_];
__device__ __align__(128) float g_kvall[(size_t)NT_ * (KVL_ + DR_)];

__device__ __align__(128) bf16 g_xhi[(size_t)NT_ * HID_],  g_xlo[(size_t)NT_ * HID_];
__device__ __align__(128) bf16 g_qanhi[(size_t)NT_ * QL_], g_qanlo[(size_t)NT_ * QL_];
__device__ __align__(128) bf16 g_kvnhi[(size_t)NT_ * KVL_],g_kvnlo[(size_t)NT_ * KVL_];
__device__ __align__(128) bf16 g_athi[(size_t)NT_ * (H_*DV_)], g_atlo[(size_t)NT_ * (H_*DV_)];
__device__ __align__(128) bf16 g_wqahi[(size_t)QL_ * HID_],        g_wqalo[(size_t)QL_ * HID_];
__device__ __align__(128) bf16 g_wqbhi[(size_t)(H_*DQK_) * QL_],   g_wqblo[(size_t)(H_*DQK_) * QL_];
__device__ __align__(128) bf16 g_wkvahi[(size_t)(KVL_+DR_) * HID_],g_wkvalo[(size_t)(KVL_+DR_) * HID_];
__device__ __align__(128) bf16 g_wkvbhi[(size_t)(H_*256) * KVL_],  g_wkvblo[(size_t)(H_*256) * KVL_];
__device__ __align__(128) bf16 g_wohi[(size_t)HID_ * (H_*DV_)],    g_wolo[(size_t)HID_ * (H_*DV_)];

// attention operand planes, packed per head
__device__ __align__(128) bf16 g_aqhi[(size_t)NT_ * H_ * DQK_], g_aqlo[(size_t)NT_ * H_ * DQK_];
__device__ __align__(128) bf16 g_akhi[(size_t)NT_ * H_ * DQK_], g_aklo[(size_t)NT_ * H_ * DQK_];
__device__ __align__(128) bf16 g_avhi[(size_t)NT_ * H_ * DV_],  g_avlo[(size_t)NT_ * H_ * DV_];

// ================= PTX helpers (baseline compute_103 features only) =========
__device__ __forceinline__ uint32_t smem_u32(const void* p) {
    uint32_t a;
    asm("{ .reg .u64 t; cvta.to.shared.u64 t, %1; cvt.u32.u64 %0, t; }" : "=r"(a) : "l"(p));
    return a;
}
__device__ __forceinline__ void cp_async16(uint32_t dst, const void* src, int src_bytes) {
    asm volatile("cp.async.cg.shared.global [%0], [%1], 16, %2;"
                 :: "r"(dst), "l"(src), "r"(src_bytes) : "memory");
}
__device__ __forceinline__ void cp_commit() {
    asm volatile("cp.async.commit_group;" ::: "memory");
}
template <int N>
__device__ __forceinline__ void cp_wait() {
    asm volatile("cp.async.wait_group %0;" :: "n"(N) : "memory");
}
__device__ __forceinline__ void ldmx4(uint32_t* r, uint32_t addr) {
    asm volatile("ldmatrix.sync.aligned.m8n8.x4.shared.b16 {%0,%1,%2,%3}, [%4];"
                 : "=r"(r[0]), "=r"(r[1]), "=r"(r[2]), "=r"(r[3]) : "r"(addr));
}
__device__ __forceinline__ void ldmx2(uint32_t* r, uint32_t addr) {
    asm volatile("ldmatrix.sync.aligned.m8n8.x2.shared.b16 {%0,%1}, [%2];"
                 : "=r"(r[0]), "=r"(r[1]) : "r"(addr));
}
__device__ __forceinline__ void ldmx4t(uint32_t* r, uint32_t addr) {
    asm volatile("ldmatrix.sync.aligned.m8n8.x4.trans.shared.b16 {%0,%1,%2,%3}, [%4];"
                 : "=r"(r[0]), "=r"(r[1]), "=r"(r[2]), "=r"(r[3]) : "r"(addr));
}
__device__ __forceinline__ void mma16816(float* c, const uint32_t* a, uint32_t b0, uint32_t b1) {
    asm("mma.sync.aligned.m16n8k16.row.col.f32.bf16.bf16.f32 "
        "{%0,%1,%2,%3}, {%4,%5,%6,%7}, {%8,%9}, {%0,%1,%2,%3};"
        : "+f"(c[0]), "+f"(c[1]), "+f"(c[2]), "+f"(c[3])
        : "r"(a[0]), "r"(a[1]), "r"(a[2]), "r"(a[3]), "r"(b0), "r"(b1));
}
__device__ __forceinline__ uint32_t packbf(float x, float y) {
    uint32_t r;
    asm("cvt.rn.bf16x2.f32 %0, %1, %2;" : "=r"(r) : "f"(y), "f"(x));
    return r;
}
__device__ __forceinline__ void split2(float x, float y, uint32_t& hi, uint32_t& lo) {
    float xh = __bfloat162float(__float2bfloat16(x));
    float yh = __bfloat162float(__float2bfloat16(y));
    hi = packbf(xh, yh);
    lo = packbf(x - xh, y - yh);
}

// ================= HMMA split-bf16 GEMM (R13 validated optimum) ==============
// CTA tile 128x128, 4 warps (128 thr) of 64x64, 2 CTAs/SM, 2-stage pipeline.
#define GBK 32
#define ROWB 80
#define APL 10240                  // plane: 128 rows * 80B
#define GBUF (4 * APL)             // Ah,Al,Bh,Bl = 40960 B per stage
#define GSMEM (2 * GBUF)           // 81920 B

struct Seg {
    const bf16 *Ah, *Al, *Wh, *Wl;
    float* C;
    bf16 *P1, *P2, *P3, *P4;
    const float* fc;
    int N, K, ldc, gx, epi;   // epi: 0=fp32 C, 1=Q(scale+rope+split), 2=KV split
};

__device__ __forceinline__ void load_tile(
    const bf16* __restrict__ g, int ld, int rowbase, int rowlim,
    int kcol, uint32_t sdst, int tid)
{
#pragma unroll
    for (int i = 0; i < 4; ++i) {
        int idx = tid + i * 128;
        int r = idx >> 2;
        int c8 = (idx & 3) << 3;
        int gr = rowbase + r;
        int ok = (gr < rowlim);
        const bf16* src = g + (size_t)(ok ? gr : rowbase) * ld + kcol + c8;
        cp_async16(sdst + r * ROWB + c8 * 2, src, ok ? 16 : 0);
    }
}

extern __shared__ uint8_t dsm[];

__global__ __launch_bounds__(128, 2) void gemm_hmma(Seg s0, Seg s1, int nb0)
{
    const Seg s = (blockIdx.x < (unsigned)nb0) ? s0 : s1;
    const int bid = (blockIdx.x < (unsigned)nb0) ? blockIdx.x : blockIdx.x - nb0;
    const int tid  = threadIdx.x;
    const int wid  = tid >> 5;
    const int lane = tid & 31;
    const int bm = (bid / s.gx) * 128;
    const int bn = (bid % s.gx) * 128;
    const int wm = (wid & 1) * 64;        // 2 warps in M
    const int wn = (wid >> 1) * 64;       // 2 warps in N
    const uint32_t sb = smem_u32(dsm);

    float acc[4][8][4];
#pragma unroll
    for (int i = 0; i < 4; i++)
#pragma unroll
        for (int j = 0; j < 8; j++)
#pragma unroll
            for (int k = 0; k < 4; k++) acc[i][j][k] = 0.f;

    const int nchunks = s.K / GBK;

    {
        uint32_t buf = sb;
        load_tile(s.Ah, s.K, bm, 1 << 30, 0, buf,           tid);
        load_tile(s.Al, s.K, bm, 1 << 30, 0, buf + APL,     tid);
        load_tile(s.Wh, s.K, bn, s.N,     0, buf + 2 * APL, tid);
        load_tile(s.Wl, s.K, bn, s.N,     0, buf + 3 * APL, tid);
        cp_commit();
    }

    const uint32_t a_off = (uint32_t)((wm + (lane & 15)) * ROWB + ((lane >> 4) << 3) * 2);
    const uint32_t b_off = (uint32_t)((wn + (lane & 7)) * ROWB + ((lane >> 3) & 1) * 16);

    for (int c = 0; c < nchunks; ++c) {
        cp_wait<0>();
        __syncthreads();              // single barrier per chunk

        if (c + 1 < nchunks) {
            uint32_t buf = sb + ((c + 1) & 1) * GBUF;
            int kcol = (c + 1) * GBK;
            load_tile(s.Ah, s.K, bm, 1 << 30, kcol, buf,           tid);
            load_tile(s.Al, s.K, bm, 1 << 30, kcol, buf + APL,     tid);
            load_tile(s.Wh, s.K, bn, s.N,     kcol, buf + 2 * APL, tid);
            load_tile(s.Wl, s.K, bn, s.N,     kcol, buf + 3 * APL, tid);
            cp_commit();
        }

        const uint32_t buf = sb + (c & 1) * GBUF;

#pragma unroll
        for (int kf = 0; kf < 2; ++kf) {
            uint32_t afr[2][4][4];
#pragma unroll
            for (int pl = 0; pl < 2; ++pl)
#pragma unroll
                for (int mi = 0; mi < 4; ++mi)
                    ldmx4(afr[pl][mi],
                          buf + pl * APL + a_off + mi * 16 * ROWB + kf * 32);
#pragma unroll
            for (int ni = 0; ni < 8; ++ni) {
                uint32_t bh[2], bl[2];
                ldmx2(bh, buf + 2 * APL + b_off + ni * 8 * ROWB + kf * 32);
                ldmx2(bl, buf + 3 * APL + b_off + ni * 8 * ROWB + kf * 32);
#pragma unroll
                for (int mi = 0; mi < 4; ++mi) {
                    float* d = acc[mi][ni];
                    mma16816(d, afr[0][mi], bh[0], bh[1]);   // hi*hi
                    mma16816(d, afr[0][mi], bl[0], bl[1]);   // hi*lo
                    mma16816(d, afr[1][mi], bh[0], bh[1]);   // lo*hi
                }
            }
        }
    }

    // -------- epilogues --------
    const int r0 = bm + wm + (lane >> 2);
    const int cb = bn + wn + (lane & 3) * 2;

    if (s.epi == 0) {
#pragma unroll
        for (int mi = 0; mi < 4; ++mi)
#pragma unroll
            for (int ni = 0; ni < 8; ++ni) {
                int col = cb + ni * 8;
                if (col < s.N) {
                    int row = r0 + mi * 16;
                    *reinterpret_cast<float2*>(&s.C[(size_t)row * s.ldc + col]) =
                        make_float2(acc[mi][ni][0], acc[mi][ni][1]);
                    *reinterpret_cast<float2*>(&s.C[(size_t)(row + 8) * s.ldc + col]) =
                        make_float2(acc[mi][ni][2], acc[mi][ni][3]);
                }
            }
    } else if (s.epi == 1) {
        const float sc = 0.07216878364870323f;   // 1/sqrt(192)
#pragma unroll
        for (int mi = 0; mi < 4; ++mi)
#pragma unroll
            for (int ni = 0; ni < 8; ++ni) {
                int col = cb + ni * 8;
                int row = r0 + mi * 16;
                int d = col % 192;
                float a0 = acc[mi][ni][0], a1 = acc[mi][ni][1];
                float a2 = acc[mi][ni][2], a3 = acc[mi][ni][3];
                if (d >= 128) {
                    int p = (d - 128) >> 1;
                    int sA = row & (S_ - 1), sB = (row + 8) & (S_ - 1);
                    float cA = s.fc[(sA * 32 + p) * 2], snA = s.fc[(sA * 32 + p) * 2 + 1];
                    float cB = s.fc[(sB * 32 + p) * 2], snB = s.fc[(sB * 32 + p) * 2 + 1];
                    float t0 = a0 * cA - a1 * snA, t1 = a0 * snA + a1 * cA;
                    float t2 = a2 * cB - a3 * snB, t3 = a2 * snB + a3 * cB;
                    a0 = t0; a1 = t1; a2 = t2; a3 = t3;
                }
                a0 *= sc; a1 *= sc; a2 *= sc; a3 *= sc;
                uint32_t hh, ll;
                split2(a0, a1, hh, ll);
                *reinterpret_cast<uint32_t*>(&s.P1[(size_t)row * 3072 + col]) = hh;
                *reinterpret_cast<uint32_t*>(&s.P2[(size_t)row * 3072 + col]) = ll;
                split2(a2, a3, hh, ll);
                *reinterpret_cast<uint32_t*>(&s.P1[(size_t)(row + 8) * 3072 + col]) = hh;
                *reinterpret_cast<uint32_t*>(&s.P2[(size_t)(row + 8) * 3072 + col]) = ll;
            }
    } else {
#pragma unroll
        for (int mi = 0; mi < 4; ++mi)
#pragma unroll
            for (int ni = 0; ni < 8; ++ni) {
                int col = cb + ni * 8;
                int row = r0 + mi * 16;
                int h = col >> 8, d = col & 255;
                bf16 *H, *L;
                size_t idx; size_t st;
                if (d < 128) { idx = ((size_t)row * 16 + h) * 192 + d;        st = (size_t)8 * 16 * 192; H = s.P1; L = s.P2; }
                else         { idx = ((size_t)row * 16 + h) * 128 + (d - 128); st = (size_t)8 * 16 * 128; H = s.P3; L = s.P4; }
                uint32_t hh, ll;
                split2(acc[mi][ni][0], acc[mi][ni][1], hh, ll);
                *reinterpret_cast<uint32_t*>(&H[idx]) = hh;
                *reinterpret_cast<uint32_t*>(&L[idx]) = ll;
                split2(acc[mi][ni][2], acc[mi][ni][3], hh, ll);
                *reinterpret_cast<uint32_t*>(&H[idx + st]) = hh;
                *reinterpret_cast<uint32_t*>(&L[idx + st]) = ll;
            }
    }
}

// ================= converts (single merged launch, MLP=4 batched) ===========
struct CTab {
    const float* s[6];
    bf16 *h[6], *l[6];
    unsigned n4[6];
    unsigned start[7];   // in blocks of 1024 float4
};

__global__ void convert_all(CTab t)
{
    unsigned b = blockIdx.x;
    int k = 0;
#pragma unroll
    for (int j = 1; j < 6; j++) if (b >= t.start[j]) k = j;
    const unsigned n4 = t.n4[k];
    const size_t base = (size_t)(b - t.start[k]) * 1024 + threadIdx.x;
    const float4* src = reinterpret_cast<const float4*>(t.s[k]);
    __nv_bfloat162* hp = reinterpret_cast<__nv_bfloat162*>(t.h[k]);
    __nv_bfloat162* lp = reinterpret_cast<__nv_bfloat162*>(t.l[k]);

    // batch 4 independent loads (warp-stride: each pass reads contiguous 512B)
    float4 v[4];
    size_t idx[4];
    int ok[4];
#pragma unroll
    for (int u = 0; u < 4; u++) {
        idx[u] = base + (size_t)u * 256;
        ok[u] = (idx[u] < n4);
        if (ok[u]) v[u] = src[idx[u]];
    }
#pragma unroll
    for (int u = 0; u < 4; u++) {
        if (!ok[u]) continue;
        bf16 h0 = __float2bfloat16(v[u].x), h1 = __float2bfloat16(v[u].y);
        bf16 h2 = __float2bfloat16(v[u].z), h3 = __float2bfloat16(v[u].w);
        bf16 l0 = __float2bfloat16(v[u].x - __bfloat162float(h0));
        bf16 l1 = __float2bfloat16(v[u].y - __bfloat162float(h1));
        bf16 l2 = __float2bfloat16(v[u].z - __bfloat162float(h2));
        bf16 l3 = __float2bfloat16(v[u].w - __bfloat162float(h3));
        hp[2*idx[u]]   = __nv_bfloat162(h0, h1); hp[2*idx[u]+1] = __nv_bfloat162(h2, h3);
        lp[2*idx[u]]   = __nv_bfloat162(l0, l1); lp[2*idx[u]+1] = __nv_bfloat162(l2, l3);
    }
}

// ---------- merged RMSNorm(q) + RMSNorm(kv) + k_pe rope/broadcast ----------
__global__ void rmsnorm_both(
    const float* __restrict__ qan, const float* __restrict__ qw,
    bf16* __restrict__ qhi, bf16* __restrict__ qlo,
    const float* __restrict__ kvall, const float* __restrict__ kvw,
    bf16* __restrict__ kvhi, bf16* __restrict__ kvlo,
    const float* __restrict__ fc,
    bf16* __restrict__ akhi, bf16* __restrict__ aklo)
{
    __shared__ float red[256];
    const int blk = blockIdx.x;
    const int isq = (blk < NT_);
    const int row = isq ? blk : blk - NT_;
    const int n = isq ? QL_ : KVL_;
    const float* p = isq ? qan + (size_t)row * QL_
                         : kvall + (size_t)row * (KVL_ + DR_);
    const float* w = isq ? qw : kvw;
    bf16* hi = isq ? qhi : kvhi;
    bf16* lo = isq ? qlo : kvlo;

    float sacc = 0.f;
    for (int i = threadIdx.x; i < n; i += 256) { float v = p[i]; sacc += v * v; }
    red[threadIdx.x] = sacc;
    __syncthreads();
    for (int o = 128; o > 0; o >>= 1) {
        if (threadIdx.x < o) red[threadIdx.x] += red[threadIdx.x + o];
        __syncthreads();
    }
    float inv = rsqrtf(red[0] / n + 1e-6f);
    for (int i = threadIdx.x * 2; i < n; i += 512) {
        float v0 = p[i] * inv * w[i];
        float v1 = p[i + 1] * inv * w[i + 1];
        uint32_t hh, ll;
        split2(v0, v1, hh, ll);
        *reinterpret_cast<uint32_t*>(&hi[(size_t)row * n + i]) = hh;
        *reinterpret_cast<uint32_t*>(&lo[(size_t)row * n + i]) = ll;
    }

    if (!isq && threadIdx.x < 32) {
        const int pr = threadIdx.x;
        const int sfx = row & (S_ - 1);
        float xr = p[KVL_ + 2 * pr];
        float xi = p[KVL_ + 2 * pr + 1];
        float c = fc[(sfx * 32 + pr) * 2], sn = fc[(sfx * 32 + pr) * 2 + 1];
        float r0 = xr * c - xi * sn, r1 = xr * sn + xi * c;
        uint32_t hh, ll;
        split2(r0, r1, hh, ll);
        size_t base = ((size_t)row * 16) * 192 + 128 + 2 * pr;
#pragma unroll
        for (int h = 0; h < 16; h++) {
            *reinterpret_cast<uint32_t*>(&akhi[base + h * 192]) = hh;
            *reinterpret_cast<uint32_t*>(&aklo[base + h * 192]) = ll;
        }
    }
}

// ================= HMMA flash attention (R9 exact shape) ====================
// BQ=64, BK=64, 128 threads (4 warps), warp = 16 q-rows x full 64 keys.
#define AQP 200
#define AVP 136
#define SM_QLO 12800
#define SM_ST  25600
#define STG_EL 43008
#define ATT_SMEM ((SM_ST + 2 * STG_EL) * 2)   // 223232 bytes

__global__ __launch_bounds__(128, 1) void attn_hmma(
    const bf16* __restrict__ qhi, const bf16* __restrict__ qlo,
    const bf16* __restrict__ khi, const bf16* __restrict__ klo,
    const bf16* __restrict__ vhi, const bf16* __restrict__ vlo,
    bf16* __restrict__ ohi, bf16* __restrict__ olo)
{
    extern __shared__ bf16 asmem[];
    const int qt = gridDim.x - 1 - blockIdx.x;    // long CTAs first
    const int h = blockIdx.y, b = blockIdx.z;
    const int tid = threadIdx.x, wid = tid >> 5, lane = tid & 31;
    const int q0 = qt * 64;
    const uint32_t sb = smem_u32(asmem);

    for (int i = tid; i < 1536; i += 128) {
        int r = i / 24, c = (i % 24) * 8;
        size_t g = ((size_t)(b * S_ + q0 + r) * H_ + h) * 192 + c;
        uint32_t d = sb + (r * AQP + c) * 2;
        cp_async16(d, qhi + g, 16);
        cp_async16(d + SM_QLO * 2, qlo + g, 16);
    }
    cp_commit();

    auto load_kv = [&](int kt, int s) {
        const int k0 = kt * 64;
        const uint32_t st = sb + (SM_ST + s * STG_EL) * 2;
        for (int i = tid; i < 1536; i += 128) {
            int r = i / 24, c = (i % 24) * 8;
            size_t g = ((size_t)(b * S_ + k0 + r) * H_ + h) * 192 + c;
            uint32_t d = st + (r * AQP + c) * 2;
            cp_async16(d, khi + g, 16);
            cp_async16(d + 12800 * 2, klo + g, 16);
        }
        for (int i = tid; i < 1024; i += 128) {
            int r = i / 16, c = (i % 16) * 8;
            size_t g = ((size_t)(b * S_ + k0 + r) * H_ + h) * 128 + c;
            uint32_t d = st + 25600 * 2 + (r * AVP + c) * 2;
            cp_async16(d, vhi + g, 16);
            cp_async16(d + 8704 * 2, vlo + g, 16);
        }
        cp_commit();
    };

    float oa[16][4];
#pragma unroll
    for (int j = 0; j < 16; j++)
#pragma unroll
        for (int e = 0; e < 4; e++) oa[j][e] = 0.f;
    float m0 = -1e30f, m1 = -1e30f, l0 = 0.f, l1 = 0.f;

    const int ntiles = qt + 1;
    load_kv(0, 0);

    const uint32_t qoff = sb + ((wid * 16 + (lane & 15)) * AQP + (lane >> 4) * 8) * 2;

    cp_wait<0>();
    __syncthreads();
    uint32_t qfh[12][4];
#pragma unroll
    for (int f = 0; f < 12; f++)
        ldmx4(qfh[f], qoff + f * 32);

    for (int kt = 0; kt < ntiles; kt++) {
        if (kt > 0) {
            cp_wait<0>();
            __syncthreads();
        }
        if (kt + 1 < ntiles) load_kv(kt + 1, (kt + 1) & 1);

        const uint32_t st = sb + (SM_ST + (kt & 1) * STG_EL) * 2;

        float c[8][4];
#pragma unroll
        for (int j = 0; j < 8; j++)
#pragma unroll
            for (int e = 0; e < 4; e++) c[j][e] = 0.f;

        const uint32_t kb = st + ((lane & 7) * AQP + (lane >> 3) * 8) * 2;
#pragma unroll
        for (int kp = 0; kp < 6; kp++) {
            uint32_t ql0[4], ql1[4];
            ldmx4(ql0, qoff + SM_QLO * 2 + kp * 64);
            ldmx4(ql1, qoff + SM_QLO * 2 + kp * 64 + 32);
#pragma unroll
            for (int nb = 0; nb < 8; nb++) {
                uint32_t kh[4], kl[4];
                ldmx4(kh, kb + nb * 8 * AQP * 2 + kp * 64);
                ldmx4(kl, kb + 12800 * 2 + nb * 8 * AQP * 2 + kp * 64);
                mma16816(c[nb], qfh[2*kp],   kh[0], kh[1]);
                mma16816(c[nb], qfh[2*kp+1], kh[2], kh[3]);
                mma16816(c[nb], qfh[2*kp],   kl[0], kl[1]);
                mma16816(c[nb], qfh[2*kp+1], kl[2], kl[3]);
                mma16816(c[nb], ql0, kh[0], kh[1]);
                mma16816(c[nb], ql1, kh[2], kh[3]);
            }
        }

        if (kt == qt) {
            const int r0 = wid * 16 + (lane >> 2);
            const int cbase = (lane & 3) * 2;
#pragma unroll
            for (int nb = 0; nb < 8; nb++) {
                int col = nb * 8 + cbase;
                if (col     > r0    ) c[nb][0] = -1e30f;
                if (col + 1 > r0    ) c[nb][1] = -1e30f;
                if (col     > r0 + 8) c[nb][2] = -1e30f;
                if (col + 1 > r0 + 8) c[nb][3] = -1e30f;
            }
        }

        float mx0 = -1e30f, mx1 = -1e30f;
#pragma unroll
        for (int nb = 0; nb < 8; nb++) {
            mx0 = fmaxf(mx0, fmaxf(c[nb][0], c[nb][1]));
            mx1 = fmaxf(mx1, fmaxf(c[nb][2], c[nb][3]));
        }
        mx0 = fmaxf(mx0, __shfl_xor_sync(0xffffffffu, mx0, 1));
        mx0 = fmaxf(mx0, __shfl_xor_sync(0xffffffffu, mx0, 2));
        mx1 = fmaxf(mx1, __shfl_xor_sync(0xffffffffu, mx1, 1));
        mx1 = fmaxf(mx1, __shfl_xor_sync(0xffffffffu, mx1, 2));
        float mn0 = fmaxf(m0, mx0), mn1 = fmaxf(m1, mx1);
        float co0 = __expf(m0 - mn0), co1 = __expf(m1 - mn1);
        m0 = mn0; m1 = mn1;
        float s0 = 0.f, s1 = 0.f;
#pragma unroll
        for (int nb = 0; nb < 8; nb++) {
            c[nb][0] = __expf(c[nb][0] - mn0); s0 += c[nb][0];
            c[nb][1] = __expf(c[nb][1] - mn0); s0 += c[nb][1];
            c[nb][2] = __expf(c[nb][2] - mn1); s1 += c[nb][2];
            c[nb][3] = __expf(c[nb][3] - mn1); s1 += c[nb][3];
        }
        s0 += __shfl_xor_sync(0xffffffffu, s0, 1);
        s0 += __shfl_xor_sync(0xffffffffu, s0, 2);
        s1 += __shfl_xor_sync(0xffffffffu, s1, 1);
        s1 += __shfl_xor_sync(0xffffffffu, s1, 2);
        l0 = l0 * co0 + s0;
        l1 = l1 * co1 + s1;
#pragma unroll
        for (int j = 0; j < 16; j++) {
            oa[j][0] *= co0; oa[j][1] *= co0;
            oa[j][2] *= co1; oa[j][3] *= co1;
        }

        const uint32_t vb = st + 25600 * 2 + ((lane & 15) * AVP + (lane >> 4) * 8) * 2;
#pragma unroll
        for (int kk = 0; kk < 4; kk++) {
            uint32_t ah[4], al[4];
            split2(c[2*kk][0],   c[2*kk][1],   ah[0], al[0]);
            split2(c[2*kk][2],   c[2*kk][3],   ah[1], al[1]);
            split2(c[2*kk+1][0], c[2*kk+1][1], ah[2], al[2]);
            split2(c[2*kk+1][2], c[2*kk+1][3], ah[3], al[3]);
#pragma unroll
            for (int n16 = 0; n16 < 8; n16++) {
                uint32_t vh[4], vl[4];
                ldmx4t(vh, vb + (kk * 16 * AVP + n16 * 16) * 2);
                ldmx4t(vl, vb + 8704 * 2 + (kk * 16 * AVP + n16 * 16) * 2);
                float* o0 = oa[2 * n16];
                float* o1 = oa[2 * n16 + 1];
                mma16816(o0, ah, vh[0], vh[1]);
                mma16816(o1, ah, vh[2], vh[3]);
                mma16816(o0, al, vh[0], vh[1]);
                mma16816(o1, al, vh[2], vh[3]);
                mma16816(o0, ah, vl[0], vl[1]);
                mma16816(o1, ah, vl[2], vl[3]);
            }
        }
    }

    const float i0 = 1.f / l0, i1 = 1.f / l1;
    const int r0 = q0 + wid * 16 + (lane >> 2);
    const size_t t0 = (size_t)(b * S_ + r0);
#pragma unroll
    for (int j = 0; j < 16; j++) {
        int col = h * 128 + j * 8 + (lane & 3) * 2;
        uint32_t hh, ll;
        split2(oa[j][0] * i0, oa[j][1] * i0, hh, ll);
        *reinterpret_cast<uint32_t*>(&ohi[t0 * (H_*DV_) + col]) = hh;
        *reinterpret_cast<uint32_t*>(&olo[t0 * (H_*DV_) + col]) = ll;
        split2(oa[j][2] * i1, oa[j][3] * i1, hh, ll);
        *reinterpret_cast<uint32_t*>(&ohi[(t0 + 8) * (H_*DV_) + col]) = hh;
        *reinterpret_cast<uint32_t*>(&olo[(t0 + 8) * (H_*DV_) + col]) = ll;
    }
}

// ---------------- launcher ----------------
extern "C" void kernel_launch(void* const* d_in, const int* in_sizes, int n_in,
                              void* d_out, int out_size)
{
    const float* x      = (const float*)d_in[0];
    const float* freqs  = (const float*)d_in[1];
    const float* wq_a   = (const float*)d_in[2];
    const float* q_an_w = (const float*)d_in[3];
    const float* wq_b   = (const float*)d_in[4];
    const float* wkv_a  = (const float*)d_in[5];
    const float* kv_n_w = (const float*)d_in[6];
    const float* wkv_b  = (const float*)d_in[7];
    const float* wo     = (const float*)d_in[8];
    float* out = (float*)d_out;

    float *qan, *kvall;
    cudaGetSymbolAddress((void**)&qan,   g_qan);
    cudaGetSymbolAddress((void**)&kvall, g_kvall);

    bf16 *xhi,*xlo,*qanhi,*qanlo,*kvnhi,*kvnlo,*athi,*atlo;
    bf16 *wqahi,*wqalo,*wqbhi,*wqblo,*wkvahi,*wkvalo,*wkvbhi,*wkvblo,*wohi,*wolo;
    bf16 *aqhi,*aqlo,*akhi,*aklo,*avhi,*avlo;
    cudaGetSymbolAddress((void**)&xhi, g_xhi);     cudaGetSymbolAddress((void**)&xlo, g_xlo);
    cudaGetSymbolAddress((void**)&qanhi, g_qanhi); cudaGetSymbolAddress((void**)&qanlo, g_qanlo);
    cudaGetSymbolAddress((void**)&kvnhi, g_kvnhi); cudaGetSymbolAddress((void**)&kvnlo, g_kvnlo);
    cudaGetSymbolAddress((void**)&athi, g_athi);   cudaGetSymbolAddress((void**)&atlo, g_atlo);
    cudaGetSymbolAddress((void**)&wqahi, g_wqahi); cudaGetSymbolAddress((void**)&wqalo, g_wqalo);
    cudaGetSymbolAddress((void**)&wqbhi, g_wqbhi); cudaGetSymbolAddress((void**)&wqblo, g_wqblo);
    cudaGetSymbolAddress((void**)&wkvahi, g_wkvahi); cudaGetSymbolAddress((void**)&wkvalo, g_wkvalo);
    cudaGetSymbolAddress((void**)&wkvbhi, g_wkvbhi); cudaGetSymbolAddress((void**)&wkvblo, g_wkvblo);
    cudaGetSymbolAddress((void**)&wohi, g_wohi);   cudaGetSymbolAddress((void**)&wolo, g_wolo);
    cudaGetSymbolAddress((void**)&aqhi, g_aqhi);   cudaGetSymbolAddress((void**)&aqlo, g_aqlo);
    cudaGetSymbolAddress((void**)&akhi, g_akhi);   cudaGetSymbolAddress((void**)&aklo, g_aklo);
    cudaGetSymbolAddress((void**)&avhi, g_avhi);   cudaGetSymbolAddress((void**)&avlo, g_avlo);

    cudaFuncSetAttribute(gemm_hmma, cudaFuncAttributeMaxDynamicSharedMemorySize, GSMEM);
    cudaFuncSetAttribute(attn_hmma, cudaFuncAttributeMaxDynamicSharedMemorySize, ATT_SMEM);

    // ---- merged input/weight converts (4 float4 per thread) ----
    CTab ct;
    const float* srcs[6] = {x, wq_a, wq_b, wkv_a, wkv_b, wo};
    bf16* his[6] = {xhi, wqahi, wqbhi, wkvahi, wkvbhi, wohi};
    bf16* los[6] = {xlo, wqalo, wqblo, wkvalo, wkvblo, wolo};
    size_t ns[6] = {(size_t)NT_*HID_, (size_t)QL_*HID_, (size_t)(H_*DQK_)*QL_,
                    (size_t)(KVL_+DR_)*HID_, (size_t)(H_*256)*KVL_, (size_t)HID_*(H_*DV_)};
    unsigned cum = 0;
    for (int i = 0; i < 6; i++) {
        ct.s[i] = srcs[i]; ct.h[i] = his[i]; ct.l[i] = los[i];
        ct.n4[i] = (unsigned)(ns[i] / 4);
        ct.start[i] = cum;
        cum += (ct.n4[i] + 1023) / 1024;
    }
    ct.start[6] = cum;
    convert_all<<<cum, 256>>>(ct);

    // ---- L1: wq_a + wkv_a (both read x planes) ----
    {
        Seg a = {xhi, xlo, wqahi, wqalo, qan, nullptr, nullptr, nullptr, nullptr,
                 freqs, QL_, HID_, QL_, QL_/128, 0};
        Seg b = {xhi, xlo, wkvahi, wkvalo, kvall, nullptr, nullptr, nullptr, nullptr,
                 freqs, KVL_+DR_, HID_, KVL_+DR_, (KVL_+DR_+127)/128, 0};
        int nb0 = (QL_/128) * (NT_/128);
        int nb1 = ((KVL_+DR_+127)/128) * (NT_/128);
        gemm_hmma<<<nb0 + nb1, 128, GSMEM>>>(a, b, nb0);
    }

    // ---- merged rmsnorms (+fused k_pe rope/broadcast) ----
    rmsnorm_both<<<2 * NT_, 256>>>(qan, q_an_w, qanhi, qanlo,
                                   kvall, kv_n_w, kvnhi, kvnlo,
                                   freqs, akhi, aklo);

    // ---- L2: wq_b (epi Q) + wkv_b (epi KV split) ----
    {
        Seg a = {qanhi, qanlo, wqbhi, wqblo, nullptr, aqhi, aqlo, nullptr, nullptr,
                 freqs, H_*DQK_, QL_, 0, (H_*DQK_)/128, 1};
        Seg b = {kvnhi, kvnlo, wkvbhi, wkvblo, nullptr, akhi, aklo, avhi, avlo,
                 freqs, H_*256, KVL_, 0, (H_*256)/128, 2};
        int nb0 = ((H_*DQK_)/128) * (NT_/128);
        int nb1 = ((H_*256)/128) * (NT_/128);
        gemm_hmma<<<nb0 + nb1, 128, GSMEM>>>(a, b, nb0);
    }

    // ---- attention (R9 exact shape) ----
    attn_hmma<<<dim3(S_ / 64, H_, B_), 128, ATT_SMEM>>>(
        aqhi, aqlo, akhi, aklo, avhi, avlo, athi, atlo);

    // ---- L3: wo ----
    {
        Seg a = {athi, atlo, wohi, wolo, out, nullptr, nullptr, nullptr, nullptr,
                 freqs, HID_, H_*DV_, HID_, HID_/128, 0};
        int nb0 = (HID_/128) * (NT_/128);
        gemm_hmma<<<nb0, 128, GSMEM>>>(a, a, nb0);
    }
}